// round 2
// baseline (speedup 1.0000x reference)
#include <cuda_runtime.h>
#include <math.h>

#define E_EDGES 800000
#define NN 50000
#define D_N 64
#define HID 128
#define D_OUT 64
#define KX 192     // 2*D_N + D_E
#define BE 64      // edges per block

typedef unsigned long long ull;

__device__ int g_idx64;                       // 1 if src/dst are int64, 0 if int32
__device__ float g_agg[(size_t)NN * D_OUT];   // scatter-sum scratch

// packed fp32x2 FMA (d = a*b + d), pack/unpack helpers
#define FMA2(d, a, b) asm("fma.rn.f32x2 %0, %1, %2, %0;" : "+l"(d) : "l"(a), "l"(b))
#define PACK2(d, f)   asm("mov.b64 %0, {%1, %1};" : "=l"(d) : "f"(f))
#define UNPACK2(lo, hi, s) asm("mov.b64 {%0, %1}, %2;" : "=f"(lo), "=f"(hi) : "l"(s))

// ---------------------------------------------------------------------------
// index dtype detection: int64 little-endian => every odd 32-bit word is 0
// ---------------------------------------------------------------------------
__global__ void detect_kernel(const unsigned int* __restrict__ raw) {
    __shared__ int any;
    if (threadIdx.x == 0) any = 0;
    __syncthreads();
    int f = 0;
    for (int i = threadIdx.x; i < 2048; i += blockDim.x)
        if (raw[2 * i + 1] != 0u) f = 1;
    if (f) atomicExch(&any, 1);
    __syncthreads();
    if (threadIdx.x == 0) g_idx64 = (any == 0) ? 1 : 0;
}

__global__ void zero_agg_kernel() {
    int i = blockIdx.x * blockDim.x + threadIdx.x;   // exactly NN*D_OUT/4 threads
    ((float4*)g_agg)[i] = make_float4(0.f, 0.f, 0.f, 0.f);
}

// ---------------------------------------------------------------------------
// Edge kernel: per block of 64 edges
//   x = [nf[src] | nf[dst] | ef]  (192)  -> H = relu(x @ [We1|Wa1] + b) (256)
//   e_pre = H_e @ We2, a_pre = H_a @ Wa2 ; msg = sigmoid(a)*(e)
//   write updated_ef, atomic-scatter msg into g_agg[dst]
// SMEM: sXT[192][68] (x transposed, padded), sW1[16][256] chunk, sH[64][256],
//       sW2[128][128] reuses the sXT+sW1 region after phase 1.
// ---------------------------------------------------------------------------
#define XS 68
#define EDGE_SMEM ((192*XS + 16*256 + 64*256) * 4 + 2 * BE * 4)

__global__ __launch_bounds__(256, 1) void edge_kernel(
    const float* __restrict__ nf, const float* __restrict__ ef,
    const int* __restrict__ rawsrc, const int* __restrict__ rawdst,
    const float* __restrict__ We1, const float* __restrict__ be1,
    const float* __restrict__ We2, const float* __restrict__ be2,
    const float* __restrict__ Wa1, const float* __restrict__ ba1,
    const float* __restrict__ Wa2, const float* __restrict__ ba2,
    float* __restrict__ ef_out)
{
    extern __shared__ float sm[];
    float* sXT = sm;                          // [192][XS]
    float* sW1 = sm + 192 * XS;               // [16][256]
    float* sH  = sm + 192 * XS + 16 * 256;    // [64][256]
    int*   sSrc = (int*)(sH + 64 * 256);
    int*   sDst = sSrc + BE;

    const int tid = threadIdx.x;
    const int tx = tid & 15;
    const int ty = tid >> 4;
    const int e0 = blockIdx.x * BE;
    const int is64 = g_idx64;

    if (tid < BE) {
        int e = e0 + tid;
        sSrc[tid] = is64 ? rawsrc[2 * e] : rawsrc[e];
    } else if (tid < 2 * BE) {
        int m = tid - BE;
        int e = e0 + m;
        sDst[m] = is64 ? rawdst[2 * e] : rawdst[e];
    }
    __syncthreads();

    // gather x into transposed smem
    {
        const int w = tid >> 5, lane = tid & 31;
        #pragma unroll
        for (int r = 0; r < 8; r++) {
            int m = w * 8 + r;
            int s = sSrc[m];
            int d = sDst[m];
            const float* ns = nf + (size_t)s * D_N;
            const float* nd = nf + (size_t)d * D_N;
            const float* ee = ef + (size_t)(e0 + m) * D_N;
            sXT[lane * XS + m]          = ns[lane];
            sXT[(lane + 32) * XS + m]   = ns[lane + 32];
            sXT[(lane + 64) * XS + m]   = nd[lane];
            sXT[(lane + 96) * XS + m]   = nd[lane + 32];
            sXT[(lane + 128) * XS + m]  = ee[lane];
            sXT[(lane + 160) * XS + m]  = ee[lane + 32];
        }
    }

    // ---- phase 1: [64,192] @ [192,256], thread tile: 4 rows x 16 cols ----
    ull acc[4][8];
    #pragma unroll
    for (int i = 0; i < 4; i++)
        #pragma unroll
        for (int j = 0; j < 8; j++) acc[i][j] = 0ull;

    for (int c = 0; c < 12; c++) {
        const int k0 = c * 16;
        __syncthreads();   // prior-chunk reads of sW1 done (and gather, on c==0)
        #pragma unroll
        for (int i = 0; i < 4; i++) {
            int fidx = tid + 256 * i;   // 1024 float4s
            int kc = fidx >> 6;
            int col = (fidx & 63) * 4;
            const float* src = (col < 128) ? (We1 + (k0 + kc) * 128 + col)
                                           : (Wa1 + (k0 + kc) * 128 + (col - 128));
            *(float4*)(sW1 + kc * 256 + col) = *(const float4*)src;
        }
        __syncthreads();
        #pragma unroll
        for (int kc = 0; kc < 16; kc++) {
            float4 xv = *(const float4*)(sXT + (k0 + kc) * XS + ty * 4);
            ull xp0, xp1, xp2, xp3;
            PACK2(xp0, xv.x); PACK2(xp1, xv.y); PACK2(xp2, xv.z); PACK2(xp3, xv.w);
            #pragma unroll
            for (int j = 0; j < 4; j++) {
                ulonglong2 wv = *(const ulonglong2*)(sW1 + kc * 256 + tx * 4 + 64 * j);
                FMA2(acc[0][2*j], xp0, wv.x); FMA2(acc[0][2*j+1], xp0, wv.y);
                FMA2(acc[1][2*j], xp1, wv.x); FMA2(acc[1][2*j+1], xp1, wv.y);
                FMA2(acc[2][2*j], xp2, wv.x); FMA2(acc[2][2*j+1], xp2, wv.y);
                FMA2(acc[3][2*j], xp3, wv.x); FMA2(acc[3][2*j+1], xp3, wv.y);
            }
        }
    }

    // bias + relu -> sH[m][n]
    #pragma unroll
    for (int j = 0; j < 4; j++) {
        int n0 = tx * 4 + 64 * j;
        const float* bsrc = (n0 < 128) ? (be1 + n0) : (ba1 + n0 - 128);
        float4 bb = *(const float4*)bsrc;
        #pragma unroll
        for (int i = 0; i < 4; i++) {
            float v0, v1, v2, v3;
            UNPACK2(v0, v1, acc[i][2*j]);
            UNPACK2(v2, v3, acc[i][2*j+1]);
            v0 = fmaxf(v0 + bb.x, 0.f);
            v1 = fmaxf(v1 + bb.y, 0.f);
            v2 = fmaxf(v2 + bb.z, 0.f);
            v3 = fmaxf(v3 + bb.w, 0.f);
            *(float4*)(sH + (ty * 4 + i) * 256 + n0) = make_float4(v0, v1, v2, v3);
        }
    }
    __syncthreads();   // sXT/sW1 reads done -> safe to overwrite with W2

    // stage W2cat[128][128] = [We2 | Wa2]
    float* sW2 = sm;
    #pragma unroll
    for (int i = 0; i < 16; i++) {
        int fidx = tid + 256 * i;   // 4096 float4s
        int k = fidx >> 5;
        int c4 = fidx & 31;
        const float* src = (c4 < 16) ? (We2 + k * 64 + c4 * 4)
                                     : (Wa2 + k * 64 + (c4 - 16) * 4);
        *(float4*)(sW2 + k * 128 + c4 * 4) = *(const float4*)src;
    }
    __syncthreads();

    // ---- phase 2: e_pre = H[:,0:128]@We2 ; a_pre = H[:,128:256]@Wa2 ----
    ull ea[4][2], aa[4][2];
    #pragma unroll
    for (int i = 0; i < 4; i++) { ea[i][0] = ea[i][1] = aa[i][0] = aa[i][1] = 0ull; }

    #pragma unroll 2
    for (int k = 0; k < 128; k++) {
        ulonglong2 we = *(const ulonglong2*)(sW2 + k * 128 + tx * 4);
        ulonglong2 wa = *(const ulonglong2*)(sW2 + k * 128 + 64 + tx * 4);
        #pragma unroll
        for (int i = 0; i < 4; i++) {
            ull hp, hq;
            PACK2(hp, sH[(ty * 4 + i) * 256 + k]);
            PACK2(hq, sH[(ty * 4 + i) * 256 + 128 + k]);
            FMA2(ea[i][0], hp, we.x); FMA2(ea[i][1], hp, we.y);
            FMA2(aa[i][0], hq, wa.x); FMA2(aa[i][1], hq, wa.y);
        }
    }

    // epilogue: gate * e_out, write updated_ef, scatter into g_agg[dst]
    const int n0 = tx * 4;
    float4 bbe = *(const float4*)(be2 + n0);
    float4 bba = *(const float4*)(ba2 + n0);
    #pragma unroll
    for (int i = 0; i < 4; i++) {
        int m = ty * 4 + i;
        int e = e0 + m;
        int d = sDst[m];
        float ev0, ev1, ev2, ev3, av0, av1, av2, av3;
        UNPACK2(ev0, ev1, ea[i][0]); UNPACK2(ev2, ev3, ea[i][1]);
        UNPACK2(av0, av1, aa[i][0]); UNPACK2(av2, av3, aa[i][1]);
        ev0 += bbe.x; ev1 += bbe.y; ev2 += bbe.z; ev3 += bbe.w;
        av0 += bba.x; av1 += bba.y; av2 += bba.z; av3 += bba.w;
        float m0 = ev0 / (1.f + expf(-av0));
        float m1 = ev1 / (1.f + expf(-av1));
        float m2 = ev2 / (1.f + expf(-av2));
        float m3 = ev3 / (1.f + expf(-av3));
        *(float4*)(ef_out + (size_t)e * D_OUT + n0) = make_float4(m0, m1, m2, m3);
        float* ap = g_agg + (size_t)d * D_OUT + n0;
        atomicAdd(ap + 0, m0);
        atomicAdd(ap + 1, m1);
        atomicAdd(ap + 2, m2);
        atomicAdd(ap + 3, m3);
    }
}

// ---------------------------------------------------------------------------
// Node kernel: x = [agg | nf] (128) -> relu(x@Wn1+bn1) @ Wn2 + bn2
// SMEM: sXT[128][68], sW1[128][128], sH[64][128]; sW2[128][64] reuses sXT.
// ---------------------------------------------------------------------------
#define NODE_SMEM ((128*XS + 128*128 + 64*128) * 4)

__global__ __launch_bounds__(256, 1) void node_kernel(
    const float* __restrict__ nf,
    const float* __restrict__ Wn1, const float* __restrict__ bn1,
    const float* __restrict__ Wn2, const float* __restrict__ bn2,
    float* __restrict__ nf_out)
{
    extern __shared__ float sm[];
    float* sXT = sm;                    // [128][XS]
    float* sW1 = sm + 128 * XS;         // [128][128]
    float* sH  = sW1 + 128 * 128;       // [64][128]

    const int tid = threadIdx.x;
    const int tx = tid & 15;
    const int ty = tid >> 4;
    const int m0 = blockIdx.x * 64;
    const int w = tid >> 5, lane = tid & 31;

    #pragma unroll
    for (int r = 0; r < 8; r++) {
        int m = w * 8 + r;
        int node = m0 + m;
        float a0 = 0.f, a1 = 0.f, f0 = 0.f, f1 = 0.f;
        if (node < NN) {
            const float* ag = g_agg + (size_t)node * D_OUT;
            const float* nn = nf + (size_t)node * D_N;
            a0 = ag[lane]; a1 = ag[lane + 32];
            f0 = nn[lane]; f1 = nn[lane + 32];
        }
        sXT[lane * XS + m]        = a0;
        sXT[(lane + 32) * XS + m] = a1;
        sXT[(lane + 64) * XS + m] = f0;
        sXT[(lane + 96) * XS + m] = f1;
    }
    #pragma unroll
    for (int i = 0; i < 16; i++) {
        int fidx = tid + 256 * i;   // 4096 float4s
        int k = fidx >> 5, c4 = fidx & 31;
        *(float4*)(sW1 + k * 128 + c4 * 4) = *(const float4*)(Wn1 + k * 128 + c4 * 4);
    }
    __syncthreads();

    // phase 1: [64,128] @ [128,128]
    ull acc[4][4];
    #pragma unroll
    for (int i = 0; i < 4; i++) { acc[i][0] = acc[i][1] = acc[i][2] = acc[i][3] = 0ull; }

    #pragma unroll 4
    for (int k = 0; k < 128; k++) {
        float4 xv = *(const float4*)(sXT + k * XS + ty * 4);
        ull xp0, xp1, xp2, xp3;
        PACK2(xp0, xv.x); PACK2(xp1, xv.y); PACK2(xp2, xv.z); PACK2(xp3, xv.w);
        #pragma unroll
        for (int j = 0; j < 2; j++) {
            ulonglong2 wv = *(const ulonglong2*)(sW1 + k * 128 + tx * 4 + 64 * j);
            FMA2(acc[0][2*j], xp0, wv.x); FMA2(acc[0][2*j+1], xp0, wv.y);
            FMA2(acc[1][2*j], xp1, wv.x); FMA2(acc[1][2*j+1], xp1, wv.y);
            FMA2(acc[2][2*j], xp2, wv.x); FMA2(acc[2][2*j+1], xp2, wv.y);
            FMA2(acc[3][2*j], xp3, wv.x); FMA2(acc[3][2*j+1], xp3, wv.y);
        }
    }
    #pragma unroll
    for (int j = 0; j < 2; j++) {
        int n0 = tx * 4 + 64 * j;
        float4 bb = *(const float4*)(bn1 + n0);
        #pragma unroll
        for (int i = 0; i < 4; i++) {
            float v0, v1, v2, v3;
            UNPACK2(v0, v1, acc[i][2*j]);
            UNPACK2(v2, v3, acc[i][2*j+1]);
            v0 = fmaxf(v0 + bb.x, 0.f);
            v1 = fmaxf(v1 + bb.y, 0.f);
            v2 = fmaxf(v2 + bb.z, 0.f);
            v3 = fmaxf(v3 + bb.w, 0.f);
            *(float4*)(sH + (ty * 4 + i) * 128 + n0) = make_float4(v0, v1, v2, v3);
        }
    }
    __syncthreads();   // sXT reads done

    float* sW2 = sm;   // [128][64]
    #pragma unroll
    for (int i = 0; i < 8; i++) {
        int fidx = tid + 256 * i;   // 2048 float4s
        int k = fidx >> 4, c4 = fidx & 15;
        *(float4*)(sW2 + k * 64 + c4 * 4) = *(const float4*)(Wn2 + k * 64 + c4 * 4);
    }
    __syncthreads();

    // phase 2: [64,128] @ [128,64]
    ull oa[4][2];
    #pragma unroll
    for (int i = 0; i < 4; i++) { oa[i][0] = oa[i][1] = 0ull; }

    #pragma unroll 4
    for (int k = 0; k < 128; k++) {
        ulonglong2 wv = *(const ulonglong2*)(sW2 + k * 64 + tx * 4);
        #pragma unroll
        for (int i = 0; i < 4; i++) {
            ull hp;
            PACK2(hp, sH[(ty * 4 + i) * 128 + k]);
            FMA2(oa[i][0], hp, wv.x); FMA2(oa[i][1], hp, wv.y);
        }
    }
    const int n0 = tx * 4;
    float4 bb = *(const float4*)(bn2 + n0);
    #pragma unroll
    for (int i = 0; i < 4; i++) {
        int node = m0 + ty * 4 + i;
        if (node < NN) {
            float v0, v1, v2, v3;
            UNPACK2(v0, v1, oa[i][0]);
            UNPACK2(v2, v3, oa[i][1]);
            *(float4*)(nf_out + (size_t)node * D_OUT + n0) =
                make_float4(v0 + bb.x, v1 + bb.y, v2 + bb.z, v3 + bb.w);
        }
    }
}

// ---------------------------------------------------------------------------
extern "C" void kernel_launch(void* const* d_in, const int* in_sizes, int n_in,
                              void* d_out, int out_size)
{
    const float* nf  = (const float*)d_in[0];
    const float* ef  = (const float*)d_in[1];
    const int*   src = (const int*)d_in[2];
    const int*   dst = (const int*)d_in[3];
    const float* We1 = (const float*)d_in[4];
    const float* be1 = (const float*)d_in[5];
    const float* We2 = (const float*)d_in[6];
    const float* be2 = (const float*)d_in[7];
    const float* Wa1 = (const float*)d_in[8];
    const float* ba1 = (const float*)d_in[9];
    const float* Wa2 = (const float*)d_in[10];
    const float* ba2 = (const float*)d_in[11];
    const float* Wn1 = (const float*)d_in[12];
    const float* bn1 = (const float*)d_in[13];
    const float* Wn2 = (const float*)d_in[14];
    const float* bn2 = (const float*)d_in[15];

    float* nf_out = (float*)d_out;
    float* ef_out = nf_out + (size_t)NN * D_OUT;

    cudaFuncSetAttribute(edge_kernel, cudaFuncAttributeMaxDynamicSharedMemorySize, EDGE_SMEM);
    cudaFuncSetAttribute(node_kernel, cudaFuncAttributeMaxDynamicSharedMemorySize, NODE_SMEM);

    detect_kernel<<<1, 256>>>((const unsigned int*)d_in[2]);
    zero_agg_kernel<<<(NN * D_OUT / 4) / 256, 256>>>();
    edge_kernel<<<E_EDGES / BE, 256, EDGE_SMEM>>>(
        nf, ef, src, dst, We1, be1, We2, be2, Wa1, ba1, Wa2, ba2, ef_out);
    node_kernel<<<(NN + 63) / 64, 256, NODE_SMEM>>>(nf, Wn1, bn1, Wn2, bn2, nf_out);
}

// round 4
// speedup vs baseline: 2.2100x; 2.2100x over previous
#include <cuda_runtime.h>
#include <cuda_fp16.h>
#include <math.h>
#include <stdint.h>

#define E_EDGES 800000
#define NN      50000
#define BE      128
typedef unsigned long long ull;

__device__ int    g_idx64;
__device__ float  g_agg[(size_t)NN * 64];
__device__ __half g_B1[6 * 256 * 72];       // GEMM1 B: 6 chunks [256 n][72 kpad] (Wh c0-2, Wl c3-5)
__device__ __half g_W2[2 * 2 * 64 * 136];   // GEMM2 B: [gate][hi/lo][64 n][136 kpad]

// ---------------- helpers ----------------------------------------------------
__device__ __forceinline__ uint32_t smem_u32(const void* p) {
    uint32_t a;
    asm("{ .reg .u64 t; cvta.to.shared.u64 t, %1; cvt.u32.u64 %0, t; }" : "=r"(a) : "l"(p));
    return a;
}
__device__ __forceinline__ void ldsm4(uint32_t* r, uint32_t addr) {
    asm volatile("ldmatrix.sync.aligned.m8n8.x4.shared.b16 {%0,%1,%2,%3}, [%4];"
                 : "=r"(r[0]), "=r"(r[1]), "=r"(r[2]), "=r"(r[3]) : "r"(addr));
}
__device__ __forceinline__ void mma16816(float* c, const uint32_t* a, uint32_t b0, uint32_t b1) {
    asm volatile("mma.sync.aligned.m16n8k16.row.col.f32.f16.f16.f32 "
                 "{%0,%1,%2,%3}, {%4,%5,%6,%7}, {%8,%9}, {%0,%1,%2,%3};"
                 : "+f"(c[0]), "+f"(c[1]), "+f"(c[2]), "+f"(c[3])
                 : "r"(a[0]), "r"(a[1]), "r"(a[2]), "r"(a[3]), "r"(b0), "r"(b1));
}
__device__ __forceinline__ void cpa16(uint32_t dst, const void* src) {
    asm volatile("cp.async.cg.shared.global [%0], [%1], 16;" :: "r"(dst), "l"(src));
}
#define CP_COMMIT() asm volatile("cp.async.commit_group;" ::: "memory")
#define CP_WAIT0()  asm volatile("cp.async.wait_group 0;" ::: "memory")
__device__ __forceinline__ void red2(float* p, float x, float y) {
    asm volatile("red.global.add.v2.f32 [%0], {%1,%2};" :: "l"(p), "f"(x), "f"(y) : "memory");
}
__device__ __forceinline__ uint32_t packh2(float x, float y) {
    __half2 h = __floats2half2_rn(x, y);
    return *(uint32_t*)&h;
}

// ---------------------------------------------------------------------------
__global__ void detect_kernel(const unsigned int* __restrict__ raw) {
    __shared__ int any;
    if (threadIdx.x == 0) any = 0;
    __syncthreads();
    int f = 0;
    for (int i = threadIdx.x; i < 2048; i += blockDim.x)
        if (raw[2 * i + 1] != 0u) f = 1;
    if (f) atomicExch(&any, 1);
    __syncthreads();
    if (threadIdx.x == 0) g_idx64 = (any == 0) ? 1 : 0;
}
__global__ void zero_agg_kernel() {
    int i = blockIdx.x * blockDim.x + threadIdx.x;
    ((float4*)g_agg)[i] = make_float4(0.f, 0.f, 0.f, 0.f);
}
// GEMM1 B prep: chunks 0-2 = Wh (k 0-63,64-127,128-191), 3-5 = Wl. n<128: We1, else Wa1.
__global__ void prep_b1(const float* __restrict__ We1, const float* __restrict__ Wa1) {
    int gi = blockIdx.x * 256 + threadIdx.x;      // 6*256*64 = 98304
    int c = gi >> 14, r = gi & 16383;
    int n = r >> 6, kk = r & 63;
    int k = 64 * (c < 3 ? c : c - 3) + kk;
    float w = (n < 128) ? We1[k * 128 + n] : Wa1[k * 128 + (n - 128)];
    __half hi = __float2half_rn(w);
    __half v = (c < 3) ? hi : __float2half_rn(w - __half2float(hi));
    g_B1[(c * 256 + n) * 72 + kk] = v;
}
// GEMM2 B prep: [gate][hi/lo][64 n][136 k]; gate0=We2, gate1=Wa2 ([128 k][64 n] row-major src)
__global__ void prep_w2(const float* __restrict__ We2, const float* __restrict__ Wa2) {
    int gi = blockIdx.x * 256 + threadIdx.x;      // 2*2*64*128 = 32768
    int g = gi >> 14, p = (gi >> 13) & 1;
    int r = gi & 8191, n = r >> 7, k = r & 127;
    const float* W = g ? Wa2 : We2;
    float w = W[k * 64 + n];
    __half hi = __float2half_rn(w);
    __half v = (p == 0) ? hi : __float2half_rn(w - __half2float(hi));
    g_W2[((g * 2 + p) * 64 + n) * 136 + k] = v;
}

// ---------------------------------------------------------------------------
// Edge kernel SMEM map (bytes):
//  phase1: A1H [128][200]h @0 (51200), A1L @51200 (51200), B1A @102400 (36864), B1B @139264 (36864)
//  phase2: HH [128][264]h @0 (67584), HL @67584 (67584), W2 @139264 (69632)
//  misc  : @208896 (sSrc 512, sDst 512, sBias 1024, sB2b 512) -> total 211456
// ---------------------------------------------------------------------------
#define OFF_A1H  0
#define OFF_A1L  51200
#define OFF_B1A  102400
#define OFF_B1B  139264
#define OFF_HH   0
#define OFF_HL   67584
#define OFF_W2   139264
#define OFF_MISC 208896
#define EDGE_SMEM 211456

__global__ __launch_bounds__(256, 1) void edge_kernel(
    const float* __restrict__ nf, const float* __restrict__ ef,
    const int* __restrict__ rawsrc, const int* __restrict__ rawdst,
    const float* __restrict__ be1, const float* __restrict__ ba1,
    const float* __restrict__ be2, const float* __restrict__ ba2,
    float* __restrict__ ef_out)
{
    extern __shared__ char smc[];
    const uint32_t smb = smem_u32(smc);
    const int tid = threadIdx.x, wid = tid >> 5, lane = tid & 31;
    const int e0 = blockIdx.x * BE;

    int*   sSrc  = (int*)(smc + OFF_MISC);
    int*   sDst  = (int*)(smc + OFF_MISC + 512);
    float* sBias = (float*)(smc + OFF_MISC + 1024);
    float* sB2b  = (float*)(smc + OFF_MISC + 2048);

    const int is64 = g_idx64;
    if (tid < BE) sSrc[tid] = is64 ? rawsrc[2 * (e0 + tid)] : rawsrc[e0 + tid];
    else { int m = tid - BE; sDst[m] = is64 ? rawdst[2 * (e0 + m)] : rawdst[e0 + m]; }

    if (tid < 64)
        ((float4*)sBias)[tid] = (tid < 32) ? ((const float4*)be1)[tid] : ((const float4*)ba1)[tid - 32];
    else if (tid < 96)
        ((float4*)sB2b)[tid - 64] = (tid < 80) ? ((const float4*)be2)[tid - 64] : ((const float4*)ba2)[tid - 80];

    // issue chunk 0 copy
    {
        const char* src = (const char*)g_B1;
        #pragma unroll
        for (int i = 0; i < 9; i++) cpa16(smb + OFF_B1A + (tid + 256 * i) * 16, src + (tid + 256 * i) * 16);
        CP_COMMIT();
    }
    __syncthreads();   // sSrc/sDst visible for gather

    // gather x -> A1H/A1L (fp16 hi/lo), 2 threads per edge
    {
        const int m = tid >> 1;
        const int fb = (tid & 1) * 24;
        const float* rowS = nf + (size_t)sSrc[m] * 64;
        const float* rowD = nf + (size_t)sDst[m] * 64;
        const float* rowE = ef + (size_t)(e0 + m) * 64;
        #pragma unroll
        for (int it = 0; it < 24; it++) {
            int f = fb + it;
            float4 v = (f < 16) ? ((const float4*)rowS)[f]
                     : (f < 32) ? ((const float4*)rowD)[f - 16]
                                : ((const float4*)rowE)[f - 32];
            uint32_t h0 = packh2(v.x, v.y), h1 = packh2(v.z, v.w);
            __half2 hh0 = *(__half2*)&h0, hh1 = *(__half2*)&h1;
            float2 f0 = __half22float2(hh0), f1 = __half22float2(hh1);
            uint32_t l0 = packh2(v.x - f0.x, v.y - f0.y), l1 = packh2(v.z - f1.x, v.w - f1.y);
            *(uint2*)(smc + OFF_A1H + m * 400 + f * 8) = make_uint2(h0, h1);
            *(uint2*)(smc + OFF_A1L + m * 400 + f * 8) = make_uint2(l0, l1);
        }
    }

    // fragment address pieces
    const int wr = wid * 16;
    const uint32_t aH = smb + OFF_A1H + (uint32_t)((wr + (lane & 15)) * 400 + ((lane >> 4) * 8) * 2);
    const uint32_t aL = aH + 51200;
    const uint32_t bln = (uint32_t)((((lane >> 4) << 3) + (lane & 7)) * 144 + (((lane >> 3) & 1) ? 16 : 0));

    // ---- GEMM1: acc[128] = [j8 0..31][4] over 16 rows x 256 cols ----
    float acc[128];
    #pragma unroll
    for (int i = 0; i < 128; i++) acc[i] = 0.f;

    for (int c = 0; c < 6; c++) {
        CP_WAIT0();
        __syncthreads();
        if (c < 5) {
            const char* src = (const char*)g_B1 + (size_t)(c + 1) * 36864;
            uint32_t dstb = smb + (((c + 1) & 1) ? OFF_B1B : OFF_B1A);
            #pragma unroll
            for (int i = 0; i < 9; i++) cpa16(dstb + (tid + 256 * i) * 16, src + (tid + 256 * i) * 16);
            CP_COMMIT();
        }
        const uint32_t bufb = smb + ((c & 1) ? OFF_B1B : OFF_B1A) + bln;
        const int kg0 = (c < 3 ? c : c - 3) * 64;
        const bool dual = (c < 3);
        #pragma unroll
        for (int ks = 0; ks < 4; ks++) {
            uint32_t ah[4], al[4];
            ldsm4(ah, aH + (kg0 + ks * 16) * 2);
            if (dual) ldsm4(al, aL + (kg0 + ks * 16) * 2);
            #pragma unroll
            for (int j2 = 0; j2 < 16; j2++) {
                uint32_t b[4];
                ldsm4(b, bufb + j2 * (16 * 144) + ks * 32);
                mma16816(&acc[(j2 * 2 + 0) * 4], ah, b[0], b[1]);
                mma16816(&acc[(j2 * 2 + 1) * 4], ah, b[2], b[3]);
                if (dual) {
                    mma16816(&acc[(j2 * 2 + 0) * 4], al, b[0], b[1]);
                    mma16816(&acc[(j2 * 2 + 1) * 4], al, b[2], b[3]);
                }
            }
        }
    }
    __syncthreads();   // all phase-1 smem reads done

    // stage W2 (69632B) async, overlapped with H epilogue
    #pragma unroll
    for (int i = 0; i < 17; i++) {
        cpa16(smb + OFF_W2 + (tid + 256 * i) * 16, (const char*)g_W2 + (tid + 256 * i) * 16);
    }
    CP_COMMIT();

    // ---- epilogue 1: bias+relu -> HH/HL fp16 ----
    {
        const int er = wr + (lane >> 2);
        const int ec = 2 * (lane & 3);
        #pragma unroll
        for (int j8 = 0; j8 < 32; j8++) {
            int cb = j8 * 8 + ec;
            float b0 = sBias[cb], b1 = sBias[cb + 1];
            float v0 = fmaxf(acc[j8 * 4 + 0] + b0, 0.f), v1 = fmaxf(acc[j8 * 4 + 1] + b1, 0.f);
            float v2 = fmaxf(acc[j8 * 4 + 2] + b0, 0.f), v3 = fmaxf(acc[j8 * 4 + 3] + b1, 0.f);
            uint32_t h01 = packh2(v0, v1);
            __half2 hh = *(__half2*)&h01; float2 hf = __half22float2(hh);
            uint32_t l01 = packh2(v0 - hf.x, v1 - hf.y);
            *(uint32_t*)(smc + OFF_HH + er * 528 + cb * 2) = h01;
            *(uint32_t*)(smc + OFF_HL + er * 528 + cb * 2) = l01;
            uint32_t h23 = packh2(v2, v3);
            __half2 hh2 = *(__half2*)&h23; float2 hf2 = __half22float2(hh2);
            uint32_t l23 = packh2(v2 - hf2.x, v3 - hf2.y);
            *(uint32_t*)(smc + OFF_HH + (er + 8) * 528 + cb * 2) = h23;
            *(uint32_t*)(smc + OFF_HL + (er + 8) * 528 + cb * 2) = l23;
        }
    }
    CP_WAIT0();
    __syncthreads();   // H + W2 ready

    // ---- GEMM2: acc2[0..31] = e_pre tile, [32..63] = a_pre tile ----
    const uint32_t hHb = smb + OFF_HH + (uint32_t)((wr + (lane & 15)) * 528 + ((lane >> 4) * 8) * 2);
    const uint32_t hLb = hHb + 67584;
    const uint32_t w2ln = (uint32_t)((((lane >> 4) << 3) + (lane & 7)) * 272 + (((lane >> 3) & 1) ? 16 : 0));
    float acc2[64];
    #pragma unroll
    for (int i = 0; i < 64; i++) acc2[i] = 0.f;

    #pragma unroll
    for (int hf = 0; hf < 2; hf++) {
        const uint32_t wh = smb + OFF_W2 + hf * 34816 + w2ln;
        const uint32_t wl = wh + 17408;
        #pragma unroll
        for (int ks = 0; ks < 8; ks++) {
            uint32_t ahh[4], ahl[4];
            uint32_t hofs = (uint32_t)((hf * 128 + ks * 16) * 2);
            ldsm4(ahh, hHb + hofs);
            ldsm4(ahl, hLb + hofs);
            #pragma unroll
            for (int j2 = 0; j2 < 4; j2++) {
                uint32_t bh[4], bl[4];
                ldsm4(bh, wh + j2 * (16 * 272) + ks * 32);
                mma16816(&acc2[hf * 32 + (j2 * 2 + 0) * 4], ahh, bh[0], bh[1]);
                mma16816(&acc2[hf * 32 + (j2 * 2 + 1) * 4], ahh, bh[2], bh[3]);
                mma16816(&acc2[hf * 32 + (j2 * 2 + 0) * 4], ahl, bh[0], bh[1]);
                mma16816(&acc2[hf * 32 + (j2 * 2 + 1) * 4], ahl, bh[2], bh[3]);
                ldsm4(bl, wl + j2 * (16 * 272) + ks * 32);
                mma16816(&acc2[hf * 32 + (j2 * 2 + 0) * 4], ahh, bl[0], bl[1]);
                mma16816(&acc2[hf * 32 + (j2 * 2 + 1) * 4], ahh, bl[2], bl[3]);
            }
        }
    }

    // ---- epilogue 2: gate, write ef_out, scatter ----
    {
        const int r0 = wr + (lane >> 2), r1 = r0 + 8;
        const int ec = 2 * (lane & 3);
        const int d0 = sDst[r0], d1 = sDst[r1];
        float* eo0 = ef_out + (size_t)(e0 + r0) * 64;
        float* eo1 = ef_out + (size_t)(e0 + r1) * 64;
        float* ag0 = g_agg + (size_t)d0 * 64;
        float* ag1 = g_agg + (size_t)d1 * 64;
        #pragma unroll
        for (int j8 = 0; j8 < 8; j8++) {
            int cb = j8 * 8 + ec;
            float be0 = sB2b[cb], be1v = sB2b[cb + 1];
            float ba0 = sB2b[64 + cb], ba1v = sB2b[64 + cb + 1];
            float ex0 = acc2[j8 * 4 + 0] + be0, ex1 = acc2[j8 * 4 + 1] + be1v;
            float ax0 = acc2[32 + j8 * 4 + 0] + ba0, ax1 = acc2[32 + j8 * 4 + 1] + ba1v;
            float m0 = ex0 / (1.f + __expf(-ax0));
            float m1 = ex1 / (1.f + __expf(-ax1));
            *(float2*)(eo0 + cb) = make_float2(m0, m1);
            red2(ag0 + cb, m0, m1);
            float ey0 = acc2[j8 * 4 + 2] + be0, ey1 = acc2[j8 * 4 + 3] + be1v;
            float ay0 = acc2[32 + j8 * 4 + 2] + ba0, ay1 = acc2[32 + j8 * 4 + 3] + ba1v;
            float n0 = ey0 / (1.f + __expf(-ay0));
            float n1 = ey1 / (1.f + __expf(-ay1));
            *(float2*)(eo1 + cb) = make_float2(n0, n1);
            red2(ag1 + cb, n0, n1);
        }
    }
}

// ---------------------------------------------------------------------------
// Node kernel (fp32x2, same as passing R1 version)
// ---------------------------------------------------------------------------
#define FMA2(d, a, b) asm("fma.rn.f32x2 %0, %1, %2, %0;" : "+l"(d) : "l"(a), "l"(b))
#define PACK2(d, f)   asm("mov.b64 %0, {%1, %1};" : "=l"(d) : "f"(f))
#define UNPACK2(lo, hi, s) asm("mov.b64 {%0, %1}, %2;" : "=f"(lo), "=f"(hi) : "l"(s))
#define XS 68
#define NODE_SMEM ((128*XS + 128*128 + 64*128) * 4)

__global__ __launch_bounds__(256, 1) void node_kernel(
    const float* __restrict__ nf,
    const float* __restrict__ Wn1, const float* __restrict__ bn1,
    const float* __restrict__ Wn2, const float* __restrict__ bn2,
    float* __restrict__ nf_out)
{
    extern __shared__ float sm[];
    float* sXT = sm;
    float* sW1 = sm + 128 * XS;
    float* sH  = sW1 + 128 * 128;
    const int tid = threadIdx.x, tx = tid & 15, ty = tid >> 4;
    const int m0 = blockIdx.x * 64;
    const int w = tid >> 5, lane = tid & 31;

    #pragma unroll
    for (int r = 0; r < 8; r++) {
        int m = w * 8 + r, node = m0 + m;
        float a0 = 0.f, a1 = 0.f, f0 = 0.f, f1 = 0.f;
        if (node < NN) {
            const float* ag = g_agg + (size_t)node * 64;
            const float* nn = nf + (size_t)node * 64;
            a0 = ag[lane]; a1 = ag[lane + 32]; f0 = nn[lane]; f1 = nn[lane + 32];
        }
        sXT[lane * XS + m] = a0; sXT[(lane + 32) * XS + m] = a1;
        sXT[(lane + 64) * XS + m] = f0; sXT[(lane + 96) * XS + m] = f1;
    }
    #pragma unroll
    for (int i = 0; i < 16; i++) {
        int fidx = tid + 256 * i, k = fidx >> 5, c4 = fidx & 31;
        *(float4*)(sW1 + k * 128 + c4 * 4) = *(const float4*)(Wn1 + k * 128 + c4 * 4);
    }
    __syncthreads();

    ull acc[4][4];
    #pragma unroll
    for (int i = 0; i < 4; i++) { acc[i][0]=acc[i][1]=acc[i][2]=acc[i][3]=0ull; }
    #pragma unroll 4
    for (int k = 0; k < 128; k++) {
        float4 xv = *(const float4*)(sXT + k * XS + ty * 4);
        ull xp0, xp1, xp2, xp3;
        PACK2(xp0, xv.x); PACK2(xp1, xv.y); PACK2(xp2, xv.z); PACK2(xp3, xv.w);
        #pragma unroll
        for (int j = 0; j < 2; j++) {
            ulonglong2 wv = *(const ulonglong2*)(sW1 + k * 128 + tx * 4 + 64 * j);
            FMA2(acc[0][2*j], xp0, wv.x); FMA2(acc[0][2*j+1], xp0, wv.y);
            FMA2(acc[1][2*j], xp1, wv.x); FMA2(acc[1][2*j+1], xp1, wv.y);
            FMA2(acc[2][2*j], xp2, wv.x); FMA2(acc[2][2*j+1], xp2, wv.y);
            FMA2(acc[3][2*j], xp3, wv.x); FMA2(acc[3][2*j+1], xp3, wv.y);
        }
    }
    #pragma unroll
    for (int j = 0; j < 2; j++) {
        int n0 = tx * 4 + 64 * j;
        float4 bb = *(const float4*)(bn1 + n0);
        #pragma unroll
        for (int i = 0; i < 4; i++) {
            float v0, v1, v2, v3;
            UNPACK2(v0, v1, acc[i][2*j]); UNPACK2(v2, v3, acc[i][2*j+1]);
            v0 = fmaxf(v0 + bb.x, 0.f); v1 = fmaxf(v1 + bb.y, 0.f);
            v2 = fmaxf(v2 + bb.z, 0.f); v3 = fmaxf(v3 + bb.w, 0.f);
            *(float4*)(sH + (ty * 4 + i) * 128 + n0) = make_float4(v0, v1, v2, v3);
        }
    }
    __syncthreads();
    float* sW2 = sm;
    #pragma unroll
    for (int i = 0; i < 8; i++) {
        int fidx = tid + 256 * i, k = fidx >> 4, c4 = fidx & 15;
        *(float4*)(sW2 + k * 64 + c4 * 4) = *(const float4*)(Wn2 + k * 64 + c4 * 4);
    }
    __syncthreads();
    ull oa[4][2];
    #pragma unroll
    for (int i = 0; i < 4; i++) { oa[i][0] = oa[i][1] = 0ull; }
    #pragma unroll 4
    for (int k = 0; k < 128; k++) {
        ulonglong2 wv = *(const ulonglong2*)(sW2 + k * 64 + tx * 4);
        #pragma unroll
        for (int i = 0; i < 4; i++) {
            ull hp; PACK2(hp, sH[(ty * 4 + i) * 128 + k]);
            FMA2(oa[i][0], hp, wv.x); FMA2(oa[i][1], hp, wv.y);
        }
    }
    const int n0 = tx * 4;
    float4 bb = *(const float4*)(bn2 + n0);
    #pragma unroll
    for (int i = 0; i < 4; i++) {
        int node = m0 + ty * 4 + i;
        if (node < NN) {
            float v0, v1, v2, v3;
            UNPACK2(v0, v1, oa[i][0]); UNPACK2(v2, v3, oa[i][1]);
            *(float4*)(nf_out + (size_t)node * 64 + n0) =
                make_float4(v0 + bb.x, v1 + bb.y, v2 + bb.z, v3 + bb.w);
        }
    }
}

// ---------------------------------------------------------------------------
extern "C" void kernel_launch(void* const* d_in, const int* in_sizes, int n_in,
                              void* d_out, int out_size)
{
    const float* nf  = (const float*)d_in[0];
    const float* ef  = (const float*)d_in[1];
    const float* We1 = (const float*)d_in[4];
    const float* be1 = (const float*)d_in[5];
    const float* We2 = (const float*)d_in[6];
    const float* be2 = (const float*)d_in[7];
    const float* Wa1 = (const float*)d_in[8];
    const float* ba1 = (const float*)d_in[9];
    const float* Wa2 = (const float*)d_in[10];
    const float* ba2 = (const float*)d_in[11];
    const float* Wn1 = (const float*)d_in[12];
    const float* bn1 = (const float*)d_in[13];
    const float* Wn2 = (const float*)d_in[14];
    const float* bn2 = (const float*)d_in[15];

    float* nf_out = (float*)d_out;
    float* ef_out = nf_out + (size_t)NN * 64;

    cudaFuncSetAttribute(edge_kernel, cudaFuncAttributeMaxDynamicSharedMemorySize, EDGE_SMEM);
    cudaFuncSetAttribute(node_kernel, cudaFuncAttributeMaxDynamicSharedMemorySize, NODE_SMEM);

    detect_kernel<<<1, 256>>>((const unsigned int*)d_in[2]);
    zero_agg_kernel<<<(NN * 64 / 4) / 256, 256>>>();
    prep_b1<<<384, 256>>>(We1, Wa1);
    prep_w2<<<128, 256>>>(We2, Wa2);
    edge_kernel<<<E_EDGES / BE, 256, EDGE_SMEM>>>(
        nf, ef, (const int*)d_in[2], (const int*)d_in[3],
        be1, ba1, be2, ba2, ef_out);
    node_kernel<<<(NN + 63) / 64, 256, NODE_SMEM>>>(nf, Wn1, bn1, Wn2, bn2, nf_out);
}

// round 5
// speedup vs baseline: 2.7429x; 1.2411x over previous
#include <cuda_runtime.h>
#include <cuda_fp16.h>
#include <math.h>
#include <stdint.h>

#define E_EDGES 800000
#define NN      50000
#define BE      128
typedef unsigned long long ull;

__device__ int    g_idx64;
__device__ float  g_agg[(size_t)NN * 64];
__device__ float  g_P[(size_t)50048 * 512];   // [node][ P_src(256) | P_dst(256) ]
__device__ __half g_B1e[2 * 256 * 72];        // ef-part W1: [hi/lo][256 n][72 kpad]
__device__ __half g_BP[2 * 512 * 72];         // P-prep W1:  [hi/lo][512 n][72 kpad]
__device__ __half g_W2[2 * 2 * 64 * 136];     // [gate][hi/lo][64 n][136 kpad]

// ---------------- helpers ----------------------------------------------------
__device__ __forceinline__ uint32_t smem_u32(const void* p) {
    uint32_t a;
    asm("{ .reg .u64 t; cvta.to.shared.u64 t, %1; cvt.u32.u64 %0, t; }" : "=r"(a) : "l"(p));
    return a;
}
__device__ __forceinline__ void ldsm4(uint32_t* r, uint32_t addr) {
    asm volatile("ldmatrix.sync.aligned.m8n8.x4.shared.b16 {%0,%1,%2,%3}, [%4];"
                 : "=r"(r[0]), "=r"(r[1]), "=r"(r[2]), "=r"(r[3]) : "r"(addr));
}
__device__ __forceinline__ void mma16816(float* c, const uint32_t* a, uint32_t b0, uint32_t b1) {
    asm volatile("mma.sync.aligned.m16n8k16.row.col.f32.f16.f16.f32 "
                 "{%0,%1,%2,%3}, {%4,%5,%6,%7}, {%8,%9}, {%0,%1,%2,%3};"
                 : "+f"(c[0]), "+f"(c[1]), "+f"(c[2]), "+f"(c[3])
                 : "r"(a[0]), "r"(a[1]), "r"(a[2]), "r"(a[3]), "r"(b0), "r"(b1));
}
__device__ __forceinline__ void cpa16(uint32_t dst, const void* src) {
    asm volatile("cp.async.cg.shared.global [%0], [%1], 16;" :: "r"(dst), "l"(src));
}
#define CP_COMMIT() asm volatile("cp.async.commit_group;" ::: "memory")
#define CP_WAIT0()  asm volatile("cp.async.wait_group 0;" ::: "memory")
__device__ __forceinline__ void red2(float* p, float x, float y) {
    asm volatile("red.global.add.v2.f32 [%0], {%1,%2};" :: "l"(p), "f"(x), "f"(y) : "memory");
}
__device__ __forceinline__ uint32_t packh2(float x, float y) {
    __half2 h = __floats2half2_rn(x, y);
    return *(uint32_t*)&h;
}

// ---------------------------------------------------------------------------
__global__ void detect_kernel(const unsigned int* __restrict__ raw) {
    __shared__ int any;
    if (threadIdx.x == 0) any = 0;
    __syncthreads();
    int f = 0;
    for (int i = threadIdx.x; i < 2048; i += blockDim.x)
        if (raw[2 * i + 1] != 0u) f = 1;
    if (f) atomicExch(&any, 1);
    __syncthreads();
    if (threadIdx.x == 0) g_idx64 = (any == 0) ? 1 : 0;
}
__global__ void zero_agg_kernel() {
    int i = blockIdx.x * blockDim.x + threadIdx.x;
    ((float4*)g_agg)[i] = make_float4(0.f, 0.f, 0.f, 0.f);
}
// ef-part of W1 (rows 128..191): [hi/lo][256 n][72 k]
__global__ void prep_b1e(const float* __restrict__ We1, const float* __restrict__ Wa1) {
    int gi = blockIdx.x * 256 + threadIdx.x;        // 2*256*64 = 32768
    int p = gi >> 14, r = gi & 16383;
    int n = r >> 6, kk = r & 63;
    int k = 128 + kk;
    float w = (n < 128) ? We1[k * 128 + n] : Wa1[k * 128 + (n - 128)];
    __half hi = __float2half_rn(w);
    __half v = (p == 0) ? hi : __float2half_rn(w - __half2float(hi));
    g_B1e[(p * 256 + n) * 72 + kk] = v;
}
// src/dst parts of W1 (rows 0..127): [hi/lo][512 nIdx][72 k], nIdx = part*256 + col
__global__ void prep_bp(const float* __restrict__ We1, const float* __restrict__ Wa1) {
    int gi = blockIdx.x * 256 + threadIdx.x;        // 2*512*64 = 65536
    int p = gi >> 15, r = gi & 32767;
    int nIdx = r >> 6, kk = r & 63;
    int part = nIdx >> 8, c = nIdx & 255;
    int k = part * 64 + kk;
    float w = (c < 128) ? We1[k * 128 + c] : Wa1[k * 128 + (c - 128)];
    __half hi = __float2half_rn(w);
    __half v = (p == 0) ? hi : __float2half_rn(w - __half2float(hi));
    g_BP[(p * 512 + nIdx) * 72 + kk] = v;
}
__global__ void prep_w2(const float* __restrict__ We2, const float* __restrict__ Wa2) {
    int gi = blockIdx.x * 256 + threadIdx.x;        // 32768
    int g = gi >> 14, p = (gi >> 13) & 1;
    int r = gi & 8191, n = r >> 7, k = r & 127;
    const float* W = g ? Wa2 : We2;
    float w = W[k * 64 + n];
    __half hi = __float2half_rn(w);
    __half v = (p == 0) ? hi : __float2half_rn(w - __half2float(hi));
    g_W2[((g * 2 + p) * 64 + n) * 136 + k] = v;
}

// ---------------------------------------------------------------------------
// prep_P: P[n][512] = nf[n] @ [W_src | W_dst], split-fp16 3-term HMMA.
// SMEM: AH[128][72]h @0, AL @18432, B hi [512][72] @36864, B lo @110592. tot 184320
// ---------------------------------------------------------------------------
#define PREP_SMEM 184320
__global__ __launch_bounds__(256, 1) void prep_P_kernel(const float* __restrict__ nf)
{
    extern __shared__ char smc[];
    const uint32_t smb = smem_u32(smc);
    const int tid = threadIdx.x, wid = tid >> 5, lane = tid & 31;
    const int m0 = blockIdx.x * 128;

    // stage B (147456 B)
    #pragma unroll
    for (int i = 0; i < 36; i++)
        cpa16(smb + 36864 + (tid + 256 * i) * 16, (const char*)g_BP + (tid + 256 * i) * 16);
    CP_COMMIT();

    // gather nf rows, split hi/lo
    {
        const int m = tid >> 1, h = tid & 1;
        const int node = m0 + m;
        const float* row = nf + (size_t)node * 64;
        #pragma unroll
        for (int it = 0; it < 8; it++) {
            int q = h * 8 + it;
            float4 v = (node < NN) ? ((const float4*)row)[q] : make_float4(0.f, 0.f, 0.f, 0.f);
            uint32_t h0 = packh2(v.x, v.y), h1 = packh2(v.z, v.w);
            __half2 hh0 = *(__half2*)&h0, hh1 = *(__half2*)&h1;
            float2 f0 = __half22float2(hh0), f1 = __half22float2(hh1);
            uint32_t l0 = packh2(v.x - f0.x, v.y - f0.y), l1 = packh2(v.z - f1.x, v.w - f1.y);
            *(uint2*)(smc + 0     + m * 144 + q * 8) = make_uint2(h0, h1);
            *(uint2*)(smc + 18432 + m * 144 + q * 8) = make_uint2(l0, l1);
        }
    }
    CP_WAIT0();
    __syncthreads();

    const int wr = wid * 16;
    const uint32_t aH = smb + (uint32_t)((wr + (lane & 15)) * 144 + ((lane >> 4) * 8) * 2);
    const uint32_t aL = aH + 18432;
    const uint32_t bln = (uint32_t)((((lane >> 4) << 3) + (lane & 7)) * 144 + (((lane >> 3) & 1) ? 16 : 0));
    const int r0 = wr + (lane >> 2);
    const int ec = 2 * (lane & 3);

    #pragma unroll
    for (int p = 0; p < 2; p++) {
        float acc[128];
        #pragma unroll
        for (int i = 0; i < 128; i++) acc[i] = 0.f;
        const uint32_t bH = smb + 36864  + (uint32_t)(p * 36864) + bln;
        const uint32_t bL = bH + 73728;
        #pragma unroll
        for (int ks = 0; ks < 4; ks++) {
            uint32_t ah[4], al[4];
            ldsm4(ah, aH + ks * 32);
            ldsm4(al, aL + ks * 32);
            #pragma unroll
            for (int j2 = 0; j2 < 16; j2++) {
                uint32_t bh[4], bl[4];
                ldsm4(bh, bH + j2 * 2304 + ks * 32);
                ldsm4(bl, bL + j2 * 2304 + ks * 32);
                mma16816(&acc[(2*j2+0)*4], ah, bh[0], bh[1]); mma16816(&acc[(2*j2+1)*4], ah, bh[2], bh[3]);
                mma16816(&acc[(2*j2+0)*4], al, bh[0], bh[1]); mma16816(&acc[(2*j2+1)*4], al, bh[2], bh[3]);
                mma16816(&acc[(2*j2+0)*4], ah, bl[0], bl[1]); mma16816(&acc[(2*j2+1)*4], ah, bl[2], bl[3]);
            }
        }
        // store to g_P
        #pragma unroll
        for (int j8 = 0; j8 < 32; j8++) {
            int cb = p * 256 + 8 * j8 + ec;
            *(float2*)(g_P + (size_t)(m0 + r0) * 512 + cb)     = make_float2(acc[4*j8+0], acc[4*j8+1]);
            *(float2*)(g_P + (size_t)(m0 + r0 + 8) * 512 + cb) = make_float2(acc[4*j8+2], acc[4*j8+3]);
        }
    }
}

// ---------------------------------------------------------------------------
// Edge kernel SMEM map:
//  phase1: A1H @0 (18432), A1L @18432 (18432), B1H @36864 (36864), B1L @73728 (36864)
//  Psum  : [128][264] f32 @0 (135168)    (after GEMM1; A1/B1 dead)
//  W2    : @135168 (69632)
//  misc  : @204800 (sSrc 512, sDst 512, sBias 1024, sB2b 512) -> 207360
// ---------------------------------------------------------------------------
#define OFF_A1H  0
#define OFF_A1L  18432
#define OFF_B1H  36864
#define OFF_B1L  73728
#define OFF_PS   0
#define OFF_W2   135168
#define OFF_MISC 204800
#define EDGE_SMEM 207360

__global__ __launch_bounds__(256, 1) void edge_kernel(
    const float* __restrict__ ef,
    const int* __restrict__ rawsrc, const int* __restrict__ rawdst,
    const float* __restrict__ be1, const float* __restrict__ ba1,
    const float* __restrict__ be2, const float* __restrict__ ba2,
    float* __restrict__ ef_out)
{
    extern __shared__ char smc[];
    const uint32_t smb = smem_u32(smc);
    const int tid = threadIdx.x, wid = tid >> 5, lane = tid & 31;
    const int e0 = blockIdx.x * BE;

    int*   sSrc  = (int*)(smc + OFF_MISC);
    int*   sDst  = (int*)(smc + OFF_MISC + 512);
    float* sBias = (float*)(smc + OFF_MISC + 1024);
    float* sB2b  = (float*)(smc + OFF_MISC + 2048);
    float* sPs   = (float*)(smc + OFF_PS);

    const int is64 = g_idx64;
    if (tid < BE) sSrc[tid] = is64 ? rawsrc[2 * (e0 + tid)] : rawsrc[e0 + tid];
    else { int m = tid - BE; sDst[m] = is64 ? rawdst[2 * (e0 + m)] : rawdst[e0 + m]; }

    if (tid < 64)
        ((float4*)sBias)[tid] = (tid < 32) ? ((const float4*)be1)[tid] : ((const float4*)ba1)[tid - 32];
    else if (tid < 96)
        ((float4*)sB2b)[tid - 64] = (tid < 80) ? ((const float4*)be2)[tid - 64] : ((const float4*)ba2)[tid - 80];

    // stage B1e (73728) + W2 (69632)
    #pragma unroll
    for (int i = 0; i < 18; i++)
        cpa16(smb + OFF_B1H + (tid + 256 * i) * 16, (const char*)g_B1e + (tid + 256 * i) * 16);
    #pragma unroll
    for (int i = 0; i < 17; i++)
        cpa16(smb + OFF_W2 + (tid + 256 * i) * 16, (const char*)g_W2 + (tid + 256 * i) * 16);
    CP_COMMIT();

    // gather ef rows, split hi/lo
    {
        const int m = tid >> 1, h = tid & 1;
        const float* row = ef + (size_t)(e0 + m) * 64;
        #pragma unroll
        for (int it = 0; it < 8; it++) {
            int q = h * 8 + it;
            float4 v = ((const float4*)row)[q];
            uint32_t h0 = packh2(v.x, v.y), h1 = packh2(v.z, v.w);
            __half2 hh0 = *(__half2*)&h0, hh1 = *(__half2*)&h1;
            float2 f0 = __half22float2(hh0), f1 = __half22float2(hh1);
            uint32_t l0 = packh2(v.x - f0.x, v.y - f0.y), l1 = packh2(v.z - f1.x, v.w - f1.y);
            *(uint2*)(smc + OFF_A1H + m * 144 + q * 8) = make_uint2(h0, h1);
            *(uint2*)(smc + OFF_A1L + m * 144 + q * 8) = make_uint2(l0, l1);
        }
    }
    CP_WAIT0();
    __syncthreads();

    const int wr = wid * 16;
    const uint32_t aH = smb + OFF_A1H + (uint32_t)((wr + (lane & 15)) * 144 + ((lane >> 4) * 8) * 2);
    const uint32_t aL = aH + 18432;
    const uint32_t bln = (uint32_t)((((lane >> 4) << 3) + (lane & 7)) * 144 + (((lane >> 3) & 1) ? 16 : 0));

    // ---- GEMM1: acc[16 rows][256 cols], K=64 (ef part only), 3 terms ----
    float acc[128];
    #pragma unroll
    for (int i = 0; i < 128; i++) acc[i] = 0.f;
    {
        const uint32_t bH = smb + OFF_B1H + bln;
        const uint32_t bL = smb + OFF_B1L + bln;
        #pragma unroll
        for (int ks = 0; ks < 4; ks++) {
            uint32_t ah[4], al[4];
            ldsm4(ah, aH + ks * 32);
            ldsm4(al, aL + ks * 32);
            #pragma unroll
            for (int j2 = 0; j2 < 16; j2++) {
                uint32_t bh[4], bl[4];
                ldsm4(bh, bH + j2 * 2304 + ks * 32);
                ldsm4(bl, bL + j2 * 2304 + ks * 32);
                mma16816(&acc[(2*j2+0)*4], ah, bh[0], bh[1]); mma16816(&acc[(2*j2+1)*4], ah, bh[2], bh[3]);
                mma16816(&acc[(2*j2+0)*4], al, bh[0], bh[1]); mma16816(&acc[(2*j2+1)*4], al, bh[2], bh[3]);
                mma16816(&acc[(2*j2+0)*4], ah, bl[0], bl[1]); mma16816(&acc[(2*j2+1)*4], ah, bl[2], bl[3]);
            }
        }
    }
    __syncthreads();   // A1/B1 reads done — region reused for Psum

    // ---- stage Psum[m][264] = P_src[src[m]] + P_dst[dst[m]][256:] (coalesced) ----
    {
        #pragma unroll
        for (int it = 0; it < 16; it++) {
            int m = wid * 16 + it;
            const float4* ps = (const float4*)(g_P + (size_t)sSrc[m] * 512);
            const float4* pd = (const float4*)(g_P + (size_t)sDst[m] * 512 + 256);
            #pragma unroll
            for (int j = 0; j < 2; j++) {
                int f4 = lane + 32 * j;
                float4 a = ps[f4], b = pd[f4];
                *(float4*)(sPs + m * 264 + f4 * 4) =
                    make_float4(a.x + b.x, a.y + b.y, a.z + b.z, a.w + b.w);
            }
        }
    }
    __syncthreads();

    // ---- epilogue 1 (in registers): H = relu(acc + Psum + bias) -> hi/lo h2 ----
    uint32_t hH[64], hL[64];
    {
        const int r0 = wr + (lane >> 2);
        const int ec = 2 * (lane & 3);
        #pragma unroll
        for (int j8 = 0; j8 < 32; j8++) {
            int cb = 8 * j8 + ec;
            float2 p0 = *(float2*)(sPs + r0 * 264 + cb);
            float2 p1 = *(float2*)(sPs + (r0 + 8) * 264 + cb);
            float b0 = sBias[cb], b1 = sBias[cb + 1];
            float v0 = fmaxf(acc[4*j8+0] + p0.x + b0, 0.f);
            float v1 = fmaxf(acc[4*j8+1] + p0.y + b1, 0.f);
            float v2 = fmaxf(acc[4*j8+2] + p1.x + b0, 0.f);
            float v3 = fmaxf(acc[4*j8+3] + p1.y + b1, 0.f);
            uint32_t h01 = packh2(v0, v1);
            __half2 q01 = *(__half2*)&h01; float2 f01 = __half22float2(q01);
            uint32_t l01 = packh2(v0 - f01.x, v1 - f01.y);
            uint32_t h23 = packh2(v2, v3);
            __half2 q23 = *(__half2*)&h23; float2 f23 = __half22float2(q23);
            uint32_t l23 = packh2(v2 - f23.x, v3 - f23.y);
            hH[2*j8]   = h01; hL[2*j8]   = l01;
            hH[2*j8+1] = h23; hL[2*j8+1] = l23;
        }
    }

    // ---- GEMM2: A from registers (C-frag == A-frag layout), B=W2 from smem ----
    const uint32_t w2ln = (uint32_t)((((lane >> 4) << 3) + (lane & 7)) * 272 + (((lane >> 3) & 1) ? 16 : 0));
    float acc2[64];
    #pragma unroll
    for (int i = 0; i < 64; i++) acc2[i] = 0.f;

    #pragma unroll
    for (int hf = 0; hf < 2; hf++) {
        const uint32_t wb = smb + OFF_W2 + (uint32_t)(hf * 34816) + w2ln;   // gate = hf
        #pragma unroll
        for (int kc = 0; kc < 8; kc++) {
            int jb = 2 * (hf * 16 + 2 * kc);
            uint32_t ah[4] = { hH[jb], hH[jb+1], hH[jb+2], hH[jb+3] };
            uint32_t al[4] = { hL[jb], hL[jb+1], hL[jb+2], hL[jb+3] };
            #pragma unroll
            for (int j2 = 0; j2 < 4; j2++) {
                uint32_t bh[4], bl[4];
                ldsm4(bh, wb + j2 * 4352 + kc * 32);
                ldsm4(bl, wb + 17408 + j2 * 4352 + kc * 32);
                float* c0 = &acc2[hf * 32 + (2*j2+0) * 4];
                float* c1 = &acc2[hf * 32 + (2*j2+1) * 4];
                mma16816(c0, ah, bh[0], bh[1]); mma16816(c1, ah, bh[2], bh[3]);
                mma16816(c0, al, bh[0], bh[1]); mma16816(c1, al, bh[2], bh[3]);
                mma16816(c0, ah, bl[0], bl[1]); mma16816(c1, ah, bl[2], bl[3]);
            }
        }
    }

    // ---- epilogue 2: gate, write ef_out, scatter ----
    {
        const int r0 = wr + (lane >> 2), r1 = r0 + 8;
        const int ec = 2 * (lane & 3);
        const int d0 = sDst[r0], d1 = sDst[r1];
        float* eo0 = ef_out + (size_t)(e0 + r0) * 64;
        float* eo1 = ef_out + (size_t)(e0 + r1) * 64;
        float* ag0 = g_agg + (size_t)d0 * 64;
        float* ag1 = g_agg + (size_t)d1 * 64;
        #pragma unroll
        for (int j8 = 0; j8 < 8; j8++) {
            int cb = j8 * 8 + ec;
            float be0 = sB2b[cb], be1v = sB2b[cb + 1];
            float ba0 = sB2b[64 + cb], ba1v = sB2b[64 + cb + 1];
            float ex0 = acc2[j8*4+0] + be0, ex1 = acc2[j8*4+1] + be1v;
            float ax0 = acc2[32 + j8*4+0] + ba0, ax1 = acc2[32 + j8*4+1] + ba1v;
            float m0 = ex0 / (1.f + __expf(-ax0));
            float m1 = ex1 / (1.f + __expf(-ax1));
            *(float2*)(eo0 + cb) = make_float2(m0, m1);
            red2(ag0 + cb, m0, m1);
            float ey0 = acc2[j8*4+2] + be0, ey1 = acc2[j8*4+3] + be1v;
            float ay0 = acc2[32 + j8*4+2] + ba0, ay1 = acc2[32 + j8*4+3] + ba1v;
            float n0 = ey0 / (1.f + __expf(-ay0));
            float n1 = ey1 / (1.f + __expf(-ay1));
            *(float2*)(eo1 + cb) = make_float2(n0, n1);
            red2(ag1 + cb, n0, n1);
        }
    }
}

// ---------------------------------------------------------------------------
// Node kernel (fp32x2, unchanged — passing since R1)
// ---------------------------------------------------------------------------
#define FMA2(d, a, b) asm("fma.rn.f32x2 %0, %1, %2, %0;" : "+l"(d) : "l"(a), "l"(b))
#define PACK2(d, f)   asm("mov.b64 %0, {%1, %1};" : "=l"(d) : "f"(f))
#define UNPACK2(lo, hi, s) asm("mov.b64 {%0, %1}, %2;" : "=f"(lo), "=f"(hi) : "l"(s))
#define XS 68
#define NODE_SMEM ((128*XS + 128*128 + 64*128) * 4)

__global__ __launch_bounds__(256, 1) void node_kernel(
    const float* __restrict__ nf,
    const float* __restrict__ Wn1, const float* __restrict__ bn1,
    const float* __restrict__ Wn2, const float* __restrict__ bn2,
    float* __restrict__ nf_out)
{
    extern __shared__ float sm[];
    float* sXT = sm;
    float* sW1 = sm + 128 * XS;
    float* sH  = sW1 + 128 * 128;
    const int tid = threadIdx.x, tx = tid & 15, ty = tid >> 4;
    const int m0 = blockIdx.x * 64;
    const int w = tid >> 5, lane = tid & 31;

    #pragma unroll
    for (int r = 0; r < 8; r++) {
        int m = w * 8 + r, node = m0 + m;
        float a0 = 0.f, a1 = 0.f, f0 = 0.f, f1 = 0.f;
        if (node < NN) {
            const float* ag = g_agg + (size_t)node * 64;
            const float* nn = nf + (size_t)node * 64;
            a0 = ag[lane]; a1 = ag[lane + 32]; f0 = nn[lane]; f1 = nn[lane + 32];
        }
        sXT[lane * XS + m] = a0; sXT[(lane + 32) * XS + m] = a1;
        sXT[(lane + 64) * XS + m] = f0; sXT[(lane + 96) * XS + m] = f1;
    }
    #pragma unroll
    for (int i = 0; i < 16; i++) {
        int fidx = tid + 256 * i, k = fidx >> 5, c4 = fidx & 31;
        *(float4*)(sW1 + k * 128 + c4 * 4) = *(const float4*)(Wn1 + k * 128 + c4 * 4);
    }
    __syncthreads();

    ull acc[4][4];
    #pragma unroll
    for (int i = 0; i < 4; i++) { acc[i][0]=acc[i][1]=acc[i][2]=acc[i][3]=0ull; }
    #pragma unroll 4
    for (int k = 0; k < 128; k++) {
        float4 xv = *(const float4*)(sXT + k * XS + ty * 4);
        ull xp0, xp1, xp2, xp3;
        PACK2(xp0, xv.x); PACK2(xp1, xv.y); PACK2(xp2, xv.z); PACK2(xp3, xv.w);
        #pragma unroll
        for (int j = 0; j < 2; j++) {
            ulonglong2 wv = *(const ulonglong2*)(sW1 + k * 128 + tx * 4 + 64 * j);
            FMA2(acc[0][2*j], xp0, wv.x); FMA2(acc[0][2*j+1], xp0, wv.y);
            FMA2(acc[1][2*j], xp1, wv.x); FMA2(acc[1][2*j+1], xp1, wv.y);
            FMA2(acc[2][2*j], xp2, wv.x); FMA2(acc[2][2*j+1], xp2, wv.y);
            FMA2(acc[3][2*j], xp3, wv.x); FMA2(acc[3][2*j+1], xp3, wv.y);
        }
    }
    #pragma unroll
    for (int j = 0; j < 2; j++) {
        int n0 = tx * 4 + 64 * j;
        float4 bb = *(const float4*)(bn1 + n0);
        #pragma unroll
        for (int i = 0; i < 4; i++) {
            float v0, v1, v2, v3;
            UNPACK2(v0, v1, acc[i][2*j]); UNPACK2(v2, v3, acc[i][2*j+1]);
            v0 = fmaxf(v0 + bb.x, 0.f); v1 = fmaxf(v1 + bb.y, 0.f);
            v2 = fmaxf(v2 + bb.z, 0.f); v3 = fmaxf(v3 + bb.w, 0.f);
            *(float4*)(sH + (ty * 4 + i) * 128 + n0) = make_float4(v0, v1, v2, v3);
        }
    }
    __syncthreads();
    float* sW2 = sm;
    #pragma unroll
    for (int i = 0; i < 8; i++) {
        int fidx = tid + 256 * i, k = fidx >> 4, c4 = fidx & 15;
        *(float4*)(sW2 + k * 64 + c4 * 4) = *(const float4*)(Wn2 + k * 64 + c4 * 4);
    }
    __syncthreads();
    ull oa[4][2];
    #pragma unroll
    for (int i = 0; i < 4; i++) { oa[i][0] = oa[i][1] = 0ull; }
    #pragma unroll 4
    for (int k = 0; k < 128; k++) {
        ulonglong2 wv = *(const ulonglong2*)(sW2 + k * 64 + tx * 4);
        #pragma unroll
        for (int i = 0; i < 4; i++) {
            ull hp; PACK2(hp, sH[(ty * 4 + i) * 128 + k]);
            FMA2(oa[i][0], hp, wv.x); FMA2(oa[i][1], hp, wv.y);
        }
    }
    const int n0 = tx * 4;
    float4 bb = *(const float4*)(bn2 + n0);
    #pragma unroll
    for (int i = 0; i < 4; i++) {
        int node = m0 + ty * 4 + i;
        if (node < NN) {
            float v0, v1, v2, v3;
            UNPACK2(v0, v1, oa[i][0]); UNPACK2(v2, v3, oa[i][1]);
            *(float4*)(nf_out + (size_t)node * 64 + n0) =
                make_float4(v0 + bb.x, v1 + bb.y, v2 + bb.z, v3 + bb.w);
        }
    }
}

// ---------------------------------------------------------------------------
extern "C" void kernel_launch(void* const* d_in, const int* in_sizes, int n_in,
                              void* d_out, int out_size)
{
    const float* nf  = (const float*)d_in[0];
    const float* ef  = (const float*)d_in[1];
    const float* We1 = (const float*)d_in[4];
    const float* be1 = (const float*)d_in[5];
    const float* We2 = (const float*)d_in[6];
    const float* be2 = (const float*)d_in[7];
    const float* Wa1 = (const float*)d_in[8];
    const float* ba1 = (const float*)d_in[9];
    const float* Wa2 = (const float*)d_in[10];
    const float* ba2 = (const float*)d_in[11];
    const float* Wn1 = (const float*)d_in[12];
    const float* bn1 = (const float*)d_in[13];
    const float* Wn2 = (const float*)d_in[14];
    const float* bn2 = (const float*)d_in[15];

    float* nf_out = (float*)d_out;
    float* ef_out = nf_out + (size_t)NN * 64;

    cudaFuncSetAttribute(prep_P_kernel, cudaFuncAttributeMaxDynamicSharedMemorySize, PREP_SMEM);
    cudaFuncSetAttribute(edge_kernel, cudaFuncAttributeMaxDynamicSharedMemorySize, EDGE_SMEM);
    cudaFuncSetAttribute(node_kernel, cudaFuncAttributeMaxDynamicSharedMemorySize, NODE_SMEM);

    detect_kernel<<<1, 256>>>((const unsigned int*)d_in[2]);
    zero_agg_kernel<<<3125, 256>>>();
    prep_b1e<<<128, 256>>>(We1, Wa1);
    prep_bp<<<256, 256>>>(We1, Wa1);
    prep_w2<<<128, 256>>>(We2, Wa2);
    prep_P_kernel<<<391, 256, PREP_SMEM>>>(nf);
    edge_kernel<<<E_EDGES / BE, 256, EDGE_SMEM>>>(
        ef, (const int*)d_in[2], (const int*)d_in[3],
        be1, ba1, be2, ba2, ef_out);
    node_kernel<<<(NN + 63) / 64, 256, NODE_SMEM>>>(nf, Wn1, bn1, Wn2, bn2, nf_out);
}

// round 6
// speedup vs baseline: 2.7455x; 1.0009x over previous
#include <cuda_runtime.h>
#include <cuda_fp16.h>
#include <math.h>
#include <stdint.h>

#define E_EDGES 800000
#define NN      50000
#define BE      128
typedef unsigned long long ull;

__device__ int    g_idx64;
__device__ float  g_agg[(size_t)NN * 64];
__device__ float  g_P[(size_t)50048 * 512];   // [node][ P_src(256) | P_dst(256) ]
__device__ __half g_B1e[2 * 256 * 72];        // ef-part W1: [hi|lo][256 n][72 kpad]
__device__ __half g_BP[2 * 512 * 72];         // P-prep W1:  [hi|lo][512 n][72 kpad]
__device__ __half g_W2[2 * 2 * 64 * 136];     // [gate][hi|lo][64 n][136 kpad]
__device__ __half g_Wn1[2 * 128 * 136];       // node W1: [hi|lo][128 n][136 kpad]
__device__ __half g_Wn2[2 * 64 * 136];        // node W2: [hi|lo][64 n][136 kpad]

// ---------------- helpers ----------------------------------------------------
__device__ __forceinline__ uint32_t smem_u32(const void* p) {
    uint32_t a;
    asm("{ .reg .u64 t; cvta.to.shared.u64 t, %1; cvt.u32.u64 %0, t; }" : "=r"(a) : "l"(p));
    return a;
}
__device__ __forceinline__ void ldsm4(uint32_t* r, uint32_t addr) {
    asm volatile("ldmatrix.sync.aligned.m8n8.x4.shared.b16 {%0,%1,%2,%3}, [%4];"
                 : "=r"(r[0]), "=r"(r[1]), "=r"(r[2]), "=r"(r[3]) : "r"(addr));
}
__device__ __forceinline__ void mma16816(float* c, const uint32_t* a, uint32_t b0, uint32_t b1) {
    asm volatile("mma.sync.aligned.m16n8k16.row.col.f32.f16.f16.f32 "
                 "{%0,%1,%2,%3}, {%4,%5,%6,%7}, {%8,%9}, {%0,%1,%2,%3};"
                 : "+f"(c[0]), "+f"(c[1]), "+f"(c[2]), "+f"(c[3])
                 : "r"(a[0]), "r"(a[1]), "r"(a[2]), "r"(a[3]), "r"(b0), "r"(b1));
}
__device__ __forceinline__ void cpa16(uint32_t dst, const void* src) {
    asm volatile("cp.async.cg.shared.global [%0], [%1], 16;" :: "r"(dst), "l"(src));
}
#define CP_COMMIT() asm volatile("cp.async.commit_group;" ::: "memory")
#define CP_WAIT0()  asm volatile("cp.async.wait_group 0;" ::: "memory")
__device__ __forceinline__ void red2(float* p, float x, float y) {
    asm volatile("red.global.add.v2.f32 [%0], {%1,%2};" :: "l"(p), "f"(x), "f"(y) : "memory");
}
__device__ __forceinline__ uint32_t packh2(float x, float y) {
    __half2 h = __floats2half2_rn(x, y);
    return *(uint32_t*)&h;
}

// ---------------------------------------------------------------------------
__global__ void detect_kernel(const unsigned int* __restrict__ raw) {
    __shared__ int any;
    if (threadIdx.x == 0) any = 0;
    __syncthreads();
    int f = 0;
    for (int i = threadIdx.x; i < 2048; i += blockDim.x)
        if (raw[2 * i + 1] != 0u) f = 1;
    if (f) atomicExch(&any, 1);
    __syncthreads();
    if (threadIdx.x == 0) g_idx64 = (any == 0) ? 1 : 0;
}
__global__ void zero_agg_kernel() {
    int i = blockIdx.x * blockDim.x + threadIdx.x;
    ((float4*)g_agg)[i] = make_float4(0.f, 0.f, 0.f, 0.f);
}
__global__ void prep_b1e(const float* __restrict__ We1, const float* __restrict__ Wa1) {
    int gi = blockIdx.x * 256 + threadIdx.x;        // 32768
    int p = gi >> 14, r = gi & 16383;
    int n = r >> 6, kk = r & 63;
    int k = 128 + kk;
    float w = (n < 128) ? We1[k * 128 + n] : Wa1[k * 128 + (n - 128)];
    __half hi = __float2half_rn(w);
    __half v = (p == 0) ? hi : __float2half_rn(w - __half2float(hi));
    g_B1e[(p * 256 + n) * 72 + kk] = v;
}
__global__ void prep_bp(const float* __restrict__ We1, const float* __restrict__ Wa1) {
    int gi = blockIdx.x * 256 + threadIdx.x;        // 65536
    int p = gi >> 15, r = gi & 32767;
    int nIdx = r >> 6, kk = r & 63;
    int part = nIdx >> 8, c = nIdx & 255;
    int k = part * 64 + kk;
    float w = (c < 128) ? We1[k * 128 + c] : Wa1[k * 128 + (c - 128)];
    __half hi = __float2half_rn(w);
    __half v = (p == 0) ? hi : __float2half_rn(w - __half2float(hi));
    g_BP[(p * 512 + nIdx) * 72 + kk] = v;
}
__global__ void prep_w2(const float* __restrict__ We2, const float* __restrict__ Wa2) {
    int gi = blockIdx.x * 256 + threadIdx.x;        // 32768
    int g = gi >> 14, p = (gi >> 13) & 1;
    int r = gi & 8191, n = r >> 7, k = r & 127;
    const float* W = g ? Wa2 : We2;
    float w = W[k * 64 + n];
    __half hi = __float2half_rn(w);
    __half v = (p == 0) ? hi : __float2half_rn(w - __half2float(hi));
    g_W2[((g * 2 + p) * 64 + n) * 136 + k] = v;
}
__global__ void prep_wn1(const float* __restrict__ Wn1) {
    int gi = blockIdx.x * 256 + threadIdx.x;        // 32768
    int p = gi >> 14, r = gi & 16383;
    int n = r >> 7, k = r & 127;
    float w = Wn1[k * 128 + n];
    __half hi = __float2half_rn(w);
    __half v = (p == 0) ? hi : __float2half_rn(w - __half2float(hi));
    g_Wn1[(p * 128 + n) * 136 + k] = v;
}
__global__ void prep_wn2(const float* __restrict__ Wn2) {
    int gi = blockIdx.x * 256 + threadIdx.x;        // 16384
    int p = gi >> 13, r = gi & 8191;
    int n = r >> 7, k = r & 127;
    float w = Wn2[k * 64 + n];
    __half hi = __float2half_rn(w);
    __half v = (p == 0) ? hi : __float2half_rn(w - __half2float(hi));
    g_Wn2[(p * 64 + n) * 136 + k] = v;
}

// ---------------------------------------------------------------------------
// prep_P: P[n][512] = nf[n] @ [W_src | W_dst], split-fp16 3-term HMMA.
// ---------------------------------------------------------------------------
#define PREP_SMEM 184320
__global__ __launch_bounds__(256, 1) void prep_P_kernel(const float* __restrict__ nf)
{
    extern __shared__ char smc[];
    const uint32_t smb = smem_u32(smc);
    const int tid = threadIdx.x, wid = tid >> 5, lane = tid & 31;
    const int m0 = blockIdx.x * 128;

    #pragma unroll
    for (int i = 0; i < 36; i++)
        cpa16(smb + 36864 + (tid + 256 * i) * 16, (const char*)g_BP + (tid + 256 * i) * 16);
    CP_COMMIT();

    {
        const int m = tid >> 1, h = tid & 1;
        const int node = m0 + m;
        const float* row = nf + (size_t)node * 64;
        #pragma unroll
        for (int it = 0; it < 8; it++) {
            int q = h * 8 + it;
            float4 v = (node < NN) ? ((const float4*)row)[q] : make_float4(0.f, 0.f, 0.f, 0.f);
            uint32_t h0 = packh2(v.x, v.y), h1 = packh2(v.z, v.w);
            __half2 hh0 = *(__half2*)&h0, hh1 = *(__half2*)&h1;
            float2 f0 = __half22float2(hh0), f1 = __half22float2(hh1);
            uint32_t l0 = packh2(v.x - f0.x, v.y - f0.y), l1 = packh2(v.z - f1.x, v.w - f1.y);
            *(uint2*)(smc + 0     + m * 144 + q * 8) = make_uint2(h0, h1);
            *(uint2*)(smc + 18432 + m * 144 + q * 8) = make_uint2(l0, l1);
        }
    }
    CP_WAIT0();
    __syncthreads();

    const int wr = wid * 16;
    const uint32_t aH = smb + (uint32_t)((wr + (lane & 15)) * 144 + ((lane >> 4) * 8) * 2);
    const uint32_t aL = aH + 18432;
    const uint32_t bln = (uint32_t)((((lane >> 4) << 3) + (lane & 7)) * 144 + (((lane >> 3) & 1) ? 16 : 0));
    const int r0 = wr + (lane >> 2);
    const int ec = 2 * (lane & 3);

    #pragma unroll
    for (int p = 0; p < 2; p++) {
        float acc[128];
        #pragma unroll
        for (int i = 0; i < 128; i++) acc[i] = 0.f;
        const uint32_t bH = smb + 36864  + (uint32_t)(p * 36864) + bln;
        const uint32_t bL = bH + 73728;
        #pragma unroll
        for (int ks = 0; ks < 4; ks++) {
            uint32_t ah[4], al[4];
            ldsm4(ah, aH + ks * 32);
            ldsm4(al, aL + ks * 32);
            #pragma unroll
            for (int j2 = 0; j2 < 16; j2++) {
                uint32_t bh[4], bl[4];
                ldsm4(bh, bH + j2 * 2304 + ks * 32);
                ldsm4(bl, bL + j2 * 2304 + ks * 32);
                mma16816(&acc[(2*j2+0)*4], ah, bh[0], bh[1]); mma16816(&acc[(2*j2+1)*4], ah, bh[2], bh[3]);
                mma16816(&acc[(2*j2+0)*4], al, bh[0], bh[1]); mma16816(&acc[(2*j2+1)*4], al, bh[2], bh[3]);
                mma16816(&acc[(2*j2+0)*4], ah, bl[0], bl[1]); mma16816(&acc[(2*j2+1)*4], ah, bl[2], bl[3]);
            }
        }
        #pragma unroll
        for (int j8 = 0; j8 < 32; j8++) {
            int cb = p * 256 + 8 * j8 + ec;
            *(float2*)(g_P + (size_t)(m0 + r0) * 512 + cb)     = make_float2(acc[4*j8+0], acc[4*j8+1]);
            *(float2*)(g_P + (size_t)(m0 + r0 + 8) * 512 + cb) = make_float2(acc[4*j8+2], acc[4*j8+3]);
        }
    }
}

// ---------------------------------------------------------------------------
// Edge kernel SMEM map (bytes):
//  A1H @0 (18432), A1L @18432 (18432), B1 @36864 (36864, hi then reloaded lo)
//  Psum @73728: [128][260] f32 (133120)  -> end 206848
//  W2 @0 after GEMM1 (69632)
//  misc @206848: sSrc 512, sDst 512, sBias 1024, sB2b 512 -> 209408
// ---------------------------------------------------------------------------
#define OFF_A1H  0
#define OFF_A1L  18432
#define OFF_B1   36864
#define OFF_PS   73728
#define OFF_W2   0
#define OFF_MISC 206848
#define EDGE_SMEM 209408
#define PSTR 260

__global__ __launch_bounds__(256, 1) void edge_kernel(
    const float* __restrict__ ef,
    const int* __restrict__ rawsrc, const int* __restrict__ rawdst,
    const float* __restrict__ be1, const float* __restrict__ ba1,
    const float* __restrict__ be2, const float* __restrict__ ba2,
    float* __restrict__ ef_out)
{
    extern __shared__ char smc[];
    const uint32_t smb = smem_u32(smc);
    const int tid = threadIdx.x, wid = tid >> 5, lane = tid & 31;
    const int e0 = blockIdx.x * BE;

    int*   sSrc  = (int*)(smc + OFF_MISC);
    int*   sDst  = (int*)(smc + OFF_MISC + 512);
    float* sBias = (float*)(smc + OFF_MISC + 1024);
    float* sB2b  = (float*)(smc + OFF_MISC + 2048);
    float* sPs   = (float*)(smc + OFF_PS);

    const int is64 = g_idx64;
    if (tid < BE) sSrc[tid] = is64 ? rawsrc[2 * (e0 + tid)] : rawsrc[e0 + tid];
    else { int m = tid - BE; sDst[m] = is64 ? rawdst[2 * (e0 + m)] : rawdst[e0 + m]; }

    if (tid < 64)
        ((float4*)sBias)[tid] = (tid < 32) ? ((const float4*)be1)[tid] : ((const float4*)ba1)[tid - 32];
    else if (tid < 96)
        ((float4*)sB2b)[tid - 64] = (tid < 80) ? ((const float4*)be2)[tid - 64] : ((const float4*)ba2)[tid - 80];

    // stage B1-hi (36864 B)
    #pragma unroll
    for (int i = 0; i < 9; i++)
        cpa16(smb + OFF_B1 + (tid + 256 * i) * 16, (const char*)g_B1e + (tid + 256 * i) * 16);
    CP_COMMIT();

    // gather ef rows, split hi/lo
    {
        const int m = tid >> 1, h = tid & 1;
        const float* row = ef + (size_t)(e0 + m) * 64;
        #pragma unroll
        for (int it = 0; it < 8; it++) {
            int q = h * 8 + it;
            float4 v = ((const float4*)row)[q];
            uint32_t h0 = packh2(v.x, v.y), h1 = packh2(v.z, v.w);
            __half2 hh0 = *(__half2*)&h0, hh1 = *(__half2*)&h1;
            float2 f0 = __half22float2(hh0), f1 = __half22float2(hh1);
            uint32_t l0 = packh2(v.x - f0.x, v.y - f0.y), l1 = packh2(v.z - f1.x, v.w - f1.y);
            *(uint2*)(smc + OFF_A1H + m * 144 + q * 8) = make_uint2(h0, h1);
            *(uint2*)(smc + OFF_A1L + m * 144 + q * 8) = make_uint2(l0, l1);
        }
    }
    CP_WAIT0();
    __syncthreads();

    const int wr = wid * 16;
    const uint32_t aH = smb + OFF_A1H + (uint32_t)((wr + (lane & 15)) * 144 + ((lane >> 4) * 8) * 2);
    const uint32_t aL = aH + 18432;
    const uint32_t bln = (uint32_t)((((lane >> 4) << 3) + (lane & 7)) * 144 + (((lane >> 3) & 1) ? 16 : 0));
    const uint32_t bB = smb + OFF_B1 + bln;

    float acc[128];
    #pragma unroll
    for (int i = 0; i < 128; i++) acc[i] = 0.f;

    // ---- GEMM1 pass1: (xh+xl)@Wh, with interleaved P gather (8 edges) ----
    #pragma unroll
    for (int ks = 0; ks < 4; ks++) {
        #pragma unroll
        for (int t = 0; t < 2; t++) {
            int m = (wid << 4) + ks * 2 + t;
            const float4* ps = (const float4*)(g_P + (size_t)sSrc[m] * 512);
            const float4* pd = (const float4*)(g_P + (size_t)sDst[m] * 512 + 256);
            #pragma unroll
            for (int j = 0; j < 2; j++) {
                int f4 = lane + 32 * j;
                float4 a = ps[f4], b = pd[f4];
                *(float4*)(sPs + m * PSTR + f4 * 4) =
                    make_float4(a.x + b.x, a.y + b.y, a.z + b.z, a.w + b.w);
            }
        }
        uint32_t ah[4], al[4];
        ldsm4(ah, aH + ks * 32);
        ldsm4(al, aL + ks * 32);
        #pragma unroll
        for (int j2 = 0; j2 < 16; j2++) {
            uint32_t bh[4];
            ldsm4(bh, bB + j2 * 2304 + ks * 32);
            mma16816(&acc[(2*j2+0)*4], ah, bh[0], bh[1]); mma16816(&acc[(2*j2+1)*4], ah, bh[2], bh[3]);
            mma16816(&acc[(2*j2+0)*4], al, bh[0], bh[1]); mma16816(&acc[(2*j2+1)*4], al, bh[2], bh[3]);
        }
    }
    __syncthreads();   // all pass1 B reads done

    // reload B1 with W-lo; overlap with remaining P gather (8 edges)
    #pragma unroll
    for (int i = 0; i < 9; i++)
        cpa16(smb + OFF_B1 + (tid + 256 * i) * 16, (const char*)g_B1e + 36864 + (tid + 256 * i) * 16);
    CP_COMMIT();
    #pragma unroll
    for (int it = 8; it < 16; it++) {
        int m = (wid << 4) + it;
        const float4* ps = (const float4*)(g_P + (size_t)sSrc[m] * 512);
        const float4* pd = (const float4*)(g_P + (size_t)sDst[m] * 512 + 256);
        #pragma unroll
        for (int j = 0; j < 2; j++) {
            int f4 = lane + 32 * j;
            float4 a = ps[f4], b = pd[f4];
            *(float4*)(sPs + m * PSTR + f4 * 4) =
                make_float4(a.x + b.x, a.y + b.y, a.z + b.z, a.w + b.w);
        }
    }
    CP_WAIT0();
    __syncthreads();

    // ---- GEMM1 pass2: xh@Wl ----
    #pragma unroll
    for (int ks = 0; ks < 4; ks++) {
        uint32_t ah[4];
        ldsm4(ah, aH + ks * 32);
        #pragma unroll
        for (int j2 = 0; j2 < 16; j2++) {
            uint32_t bl[4];
            ldsm4(bl, bB + j2 * 2304 + ks * 32);
            mma16816(&acc[(2*j2+0)*4], ah, bl[0], bl[1]); mma16816(&acc[(2*j2+1)*4], ah, bl[2], bl[3]);
        }
    }
    __syncthreads();   // A1/B1 dead

    // stage W2 into @0 (overlapped with epilogue 1)
    #pragma unroll
    for (int i = 0; i < 17; i++)
        cpa16(smb + OFF_W2 + (tid + 256 * i) * 16, (const char*)g_W2 + (tid + 256 * i) * 16);
    CP_COMMIT();

    // ---- epilogue 1: H = relu(acc + Psum + bias) -> hi/lo h2 regs ----
    uint32_t hH[64], hL[64];
    {
        const int r0 = wr + (lane >> 2);
        const int ec = 2 * (lane & 3);
        #pragma unroll
        for (int j8 = 0; j8 < 32; j8++) {
            int cb = 8 * j8 + ec;
            float2 p0 = *(float2*)(sPs + r0 * PSTR + cb);
            float2 p1 = *(float2*)(sPs + (r0 + 8) * PSTR + cb);
            float b0 = sBias[cb], b1 = sBias[cb + 1];
            float v0 = fmaxf(acc[4*j8+0] + p0.x + b0, 0.f);
            float v1 = fmaxf(acc[4*j8+1] + p0.y + b1, 0.f);
            float v2 = fmaxf(acc[4*j8+2] + p1.x + b0, 0.f);
            float v3 = fmaxf(acc[4*j8+3] + p1.y + b1, 0.f);
            uint32_t h01 = packh2(v0, v1);
            __half2 q01 = *(__half2*)&h01; float2 f01 = __half22float2(q01);
            uint32_t l01 = packh2(v0 - f01.x, v1 - f01.y);
            uint32_t h23 = packh2(v2, v3);
            __half2 q23 = *(__half2*)&h23; float2 f23 = __half22float2(q23);
            uint32_t l23 = packh2(v2 - f23.x, v3 - f23.y);
            hH[2*j8]   = h01; hL[2*j8]   = l01;
            hH[2*j8+1] = h23; hL[2*j8+1] = l23;
        }
    }
    CP_WAIT0();
    __syncthreads();

    // ---- GEMM2: A from registers, B=W2 ----
    const uint32_t w2ln = (uint32_t)((((lane >> 4) << 3) + (lane & 7)) * 272 + (((lane >> 3) & 1) ? 16 : 0));
    float acc2[64];
    #pragma unroll
    for (int i = 0; i < 64; i++) acc2[i] = 0.f;

    #pragma unroll
    for (int hf = 0; hf < 2; hf++) {
        const uint32_t wb = smb + OFF_W2 + (uint32_t)(hf * 34816) + w2ln;
        #pragma unroll
        for (int kc = 0; kc < 8; kc++) {
            int jb = 2 * (hf * 16 + 2 * kc);
            uint32_t ah[4] = { hH[jb], hH[jb+1], hH[jb+2], hH[jb+3] };
            uint32_t al[4] = { hL[jb], hL[jb+1], hL[jb+2], hL[jb+3] };
            #pragma unroll
            for (int j2 = 0; j2 < 4; j2++) {
                uint32_t bh[4], bl[4];
                ldsm4(bh, wb + j2 * 4352 + kc * 32);
                ldsm4(bl, wb + 17408 + j2 * 4352 + kc * 32);
                float* c0 = &acc2[hf * 32 + (2*j2+0) * 4];
                float* c1 = &acc2[hf * 32 + (2*j2+1) * 4];
                mma16816(c0, ah, bh[0], bh[1]); mma16816(c1, ah, bh[2], bh[3]);
                mma16816(c0, al, bh[0], bh[1]); mma16816(c1, al, bh[2], bh[3]);
                mma16816(c0, ah, bl[0], bl[1]); mma16816(c1, ah, bl[2], bl[3]);
            }
        }
    }

    // ---- epilogue 2 ----
    {
        const int r0 = wr + (lane >> 2), r1 = r0 + 8;
        const int ec = 2 * (lane & 3);
        const int d0 = sDst[r0], d1 = sDst[r1];
        float* eo0 = ef_out + (size_t)(e0 + r0) * 64;
        float* eo1 = ef_out + (size_t)(e0 + r1) * 64;
        float* ag0 = g_agg + (size_t)d0 * 64;
        float* ag1 = g_agg + (size_t)d1 * 64;
        #pragma unroll
        for (int j8 = 0; j8 < 8; j8++) {
            int cb = j8 * 8 + ec;
            float be0 = sB2b[cb], be1v = sB2b[cb + 1];
            float ba0 = sB2b[64 + cb], ba1v = sB2b[64 + cb + 1];
            float ex0 = acc2[j8*4+0] + be0, ex1 = acc2[j8*4+1] + be1v;
            float ax0 = acc2[32 + j8*4+0] + ba0, ax1 = acc2[32 + j8*4+1] + ba1v;
            float m0 = ex0 / (1.f + __expf(-ax0));
            float m1 = ex1 / (1.f + __expf(-ax1));
            *(float2*)(eo0 + cb) = make_float2(m0, m1);
            red2(ag0 + cb, m0, m1);
            float ey0 = acc2[j8*4+2] + be0, ey1 = acc2[j8*4+3] + be1v;
            float ay0 = acc2[32 + j8*4+2] + ba0, ay1 = acc2[32 + j8*4+3] + ba1v;
            float n0 = ey0 / (1.f + __expf(-ay0));
            float n1 = ey1 / (1.f + __expf(-ay1));
            *(float2*)(eo1 + cb) = make_float2(n0, n1);
            red2(ag1 + cb, n0, n1);
        }
    }
}

// ---------------------------------------------------------------------------
// Node kernel (HMMA 3-term): x = [agg|nf] (K=128) -> H (128) -> out (64)
// SMEM: A hi @0 (34816), A lo @34816, B1n hi @69632, lo @104448,
//       W2n @139264 (34816), bias @174080 -> 174848
// ---------------------------------------------------------------------------
#define NOFF_B1  69632
#define NOFF_W2  139264
#define NOFF_MSC 174080
#define NODE_SMEM 174848

__global__ __launch_bounds__(256, 1) void node_kernel(
    const float* __restrict__ nf,
    const float* __restrict__ bn1, const float* __restrict__ bn2,
    float* __restrict__ nf_out)
{
    extern __shared__ char smc[];
    const uint32_t smb = smem_u32(smc);
    const int tid = threadIdx.x, wid = tid >> 5, lane = tid & 31;
    const int m0 = blockIdx.x * 128;
    float* sB1b = (float*)(smc + NOFF_MSC);
    float* sB2b = (float*)(smc + NOFF_MSC + 512);

    // stage B1n (69632) + W2n (34816)
    #pragma unroll
    for (int i = 0; i < 17; i++)
        cpa16(smb + NOFF_B1 + (tid + 256 * i) * 16, (const char*)g_Wn1 + (tid + 256 * i) * 16);
    #pragma unroll
    for (int i = 0; i < 9; i++) {
        int idx = tid + 256 * i;
        if (idx < 2176) cpa16(smb + NOFF_W2 + idx * 16, (const char*)g_Wn2 + idx * 16);
    }
    CP_COMMIT();

    if (tid < 32) ((float4*)sB1b)[tid] = ((const float4*)bn1)[tid];
    else if (tid < 48) ((float4*)sB2b)[tid - 32] = ((const float4*)bn2)[tid - 32];

    // gather x = [agg | nf], split hi/lo
    {
        const int m = tid >> 1, h = tid & 1;
        const int node = m0 + m;
        const float4* src = (h == 0) ? (const float4*)(g_agg + (size_t)node * 64)
                                     : (const float4*)(nf + (size_t)node * 64);
        #pragma unroll
        for (int it = 0; it < 16; it++) {
            float4 v = (node < NN) ? src[it] : make_float4(0.f, 0.f, 0.f, 0.f);
            int k = h * 64 + it * 4;
            uint32_t h0 = packh2(v.x, v.y), h1 = packh2(v.z, v.w);
            __half2 hh0 = *(__half2*)&h0, hh1 = *(__half2*)&h1;
            float2 f0 = __half22float2(hh0), f1 = __half22float2(hh1);
            uint32_t l0 = packh2(v.x - f0.x, v.y - f0.y), l1 = packh2(v.z - f1.x, v.w - f1.y);
            *(uint2*)(smc + 0     + m * 272 + k * 2) = make_uint2(h0, h1);
            *(uint2*)(smc + 34816 + m * 272 + k * 2) = make_uint2(l0, l1);
        }
    }
    CP_WAIT0();
    __syncthreads();

    const int wr = wid * 16;
    const uint32_t aH = smb + (uint32_t)((wr + (lane & 15)) * 272 + ((lane >> 4) * 8) * 2);
    const uint32_t aL = aH + 34816;
    const uint32_t bln = (uint32_t)((((lane >> 4) << 3) + (lane & 7)) * 272 + (((lane >> 3) & 1) ? 16 : 0));

    // ---- GEMM1: [16 rows][128 cols], K=128, 3-term ----
    float acc[64];
    #pragma unroll
    for (int i = 0; i < 64; i++) acc[i] = 0.f;
    {
        const uint32_t bH = smb + NOFF_B1 + bln;
        const uint32_t bL = bH + 34816;
        #pragma unroll
        for (int ks = 0; ks < 8; ks++) {
            uint32_t ah[4], al[4];
            ldsm4(ah, aH + ks * 32);
            ldsm4(al, aL + ks * 32);
            #pragma unroll
            for (int j2 = 0; j2 < 8; j2++) {
                uint32_t bh[4], bl[4];
                ldsm4(bh, bH + j2 * 4352 + ks * 32);
                ldsm4(bl, bL + j2 * 4352 + ks * 32);
                float* c0 = &acc[(2*j2+0)*4];
                float* c1 = &acc[(2*j2+1)*4];
                mma16816(c0, ah, bh[0], bh[1]); mma16816(c1, ah, bh[2], bh[3]);
                mma16816(c0, al, bh[0], bh[1]); mma16816(c1, al, bh[2], bh[3]);
                mma16816(c0, ah, bl[0], bl[1]); mma16816(c1, ah, bl[2], bl[3]);
            }
        }
    }

    // epilogue 1: bias+relu -> hi/lo regs
    uint32_t hH[32], hL[32];
    {
        const int ec = 2 * (lane & 3);
        #pragma unroll
        for (int j8 = 0; j8 < 16; j8++) {
            int cb = 8 * j8 + ec;
            float b0 = sB1b[cb], b1 = sB1b[cb + 1];
            float v0 = fmaxf(acc[4*j8+0] + b0, 0.f);
            float v1 = fmaxf(acc[4*j8+1] + b1, 0.f);
            float v2 = fmaxf(acc[4*j8+2] + b0, 0.f);
            float v3 = fmaxf(acc[4*j8+3] + b1, 0.f);
            uint32_t h01 = packh2(v0, v1);
            __half2 q01 = *(__half2*)&h01; float2 f01 = __half22float2(q01);
            uint32_t l01 = packh2(v0 - f01.x, v1 - f01.y);
            uint32_t h23 = packh2(v2, v3);
            __half2 q23 = *(__half2*)&h23; float2 f23 = __half22float2(q23);
            uint32_t l23 = packh2(v2 - f23.x, v3 - f23.y);
            hH[2*j8] = h01; hL[2*j8] = l01;
            hH[2*j8+1] = h23; hL[2*j8+1] = l23;
        }
    }

    // ---- GEMM2: [16 rows][64], K=128, A from regs ----
    float acc2[32];
    #pragma unroll
    for (int i = 0; i < 32; i++) acc2[i] = 0.f;
    {
        const uint32_t wb = smb + NOFF_W2 + bln;
        #pragma unroll
        for (int kc = 0; kc < 8; kc++) {
            uint32_t ah[4] = { hH[4*kc], hH[4*kc+1], hH[4*kc+2], hH[4*kc+3] };
            uint32_t al[4] = { hL[4*kc], hL[4*kc+1], hL[4*kc+2], hL[4*kc+3] };
            #pragma unroll
            for (int j2 = 0; j2 < 4; j2++) {
                uint32_t bh[4], bl[4];
                ldsm4(bh, wb + j2 * 4352 + kc * 32);
                ldsm4(bl, wb + 17408 + j2 * 4352 + kc * 32);
                float* c0 = &acc2[(2*j2+0)*4];
                float* c1 = &acc2[(2*j2+1)*4];
                mma16816(c0, ah, bh[0], bh[1]); mma16816(c1, ah, bh[2], bh[3]);
                mma16816(c0, al, bh[0], bh[1]); mma16816(c1, al, bh[2], bh[3]);
                mma16816(c0, ah, bl[0], bl[1]); mma16816(c1, ah, bl[2], bl[3]);
            }
        }
    }

    // store
    {
        const int r0 = wr + (lane >> 2);
        const int ec = 2 * (lane & 3);
        const int n0 = m0 + r0, n1 = n0 + 8;
        #pragma unroll
        for (int j8 = 0; j8 < 8; j8++) {
            int cb = 8 * j8 + ec;
            float b0 = sB2b[cb], b1 = sB2b[cb + 1];
            if (n0 < NN)
                *(float2*)(nf_out + (size_t)n0 * 64 + cb) =
                    make_float2(acc2[4*j8+0] + b0, acc2[4*j8+1] + b1);
            if (n1 < NN)
                *(float2*)(nf_out + (size_t)n1 * 64 + cb) =
                    make_float2(acc2[4*j8+2] + b0, acc2[4*j8+3] + b1);
        }
    }
}

// ---------------------------------------------------------------------------
extern "C" void kernel_launch(void* const* d_in, const int* in_sizes, int n_in,
                              void* d_out, int out_size)
{
    const float* nf  = (const float*)d_in[0];
    const float* ef  = (const float*)d_in[1];
    const float* We1 = (const float*)d_in[4];
    const float* be1 = (const float*)d_in[5];
    const float* We2 = (const float*)d_in[6];
    const float* be2 = (const float*)d_in[7];
    const float* Wa1 = (const float*)d_in[8];
    const float* ba1 = (const float*)d_in[9];
    const float* Wa2 = (const float*)d_in[10];
    const float* ba2 = (const float*)d_in[11];
    const float* Wn1 = (const float*)d_in[12];
    const float* bn1 = (const float*)d_in[13];
    const float* Wn2 = (const float*)d_in[14];
    const float* bn2 = (const float*)d_in[15];

    float* nf_out = (float*)d_out;
    float* ef_out = nf_out + (size_t)NN * 64;

    cudaFuncSetAttribute(prep_P_kernel, cudaFuncAttributeMaxDynamicSharedMemorySize, PREP_SMEM);
    cudaFuncSetAttribute(edge_kernel, cudaFuncAttributeMaxDynamicSharedMemorySize, EDGE_SMEM);
    cudaFuncSetAttribute(node_kernel, cudaFuncAttributeMaxDynamicSharedMemorySize, NODE_SMEM);

    detect_kernel<<<1, 256>>>((const unsigned int*)d_in[2]);
    zero_agg_kernel<<<3125, 256>>>();
    prep_b1e<<<128, 256>>>(We1, Wa1);
    prep_bp<<<256, 256>>>(We1, Wa1);
    prep_w2<<<128, 256>>>(We2, Wa2);
    prep_wn1<<<128, 256>>>(Wn1);
    prep_wn2<<<64, 256>>>(Wn2);
    prep_P_kernel<<<391, 256, PREP_SMEM>>>(nf);
    edge_kernel<<<E_EDGES / BE, 256, EDGE_SMEM>>>(
        ef, (const int*)d_in[2], (const int*)d_in[3],
        be1, ba1, be2, ba2, ef_out);
    node_kernel<<<391, 256, NODE_SMEM>>>(nf, bn1, bn2, nf_out);
}